// round 8
// baseline (speedup 1.0000x reference)
#include <cuda_runtime.h>

#define D 64
#define NB 1024
#define XS 68   // float smem row stride
#define XD 66   // ull smem row stride (528B, 16B-aligned)

// Scratch (allocation-free rule: __device__ globals)
__device__ __align__(16) float g_Wt[8 * D * D];    // Wt[m][e*64+d] = W[m][d*64+e]
__device__ __align__(16) float g_UA[NB * 8 * D];   // u1 + S
__device__ __align__(16) float g_UB[NB * 8 * D];   // S * u1
__device__ __align__(16) float g_dise[NB * D];     // emb_dise
__device__ int g_cnt[NB];                          // completion counters

typedef unsigned long long ull;

__device__ __forceinline__ float leaky(float x) { return fmaxf(x, 0.2f * x); }
__device__ __forceinline__ float avgw(int cnt)  { return cnt > 0 ? 1.0f / ((float)cnt + 1e-8f) : 0.0f; }

__device__ __forceinline__ ull pack2(float x, float y) {
    ull r; asm("mov.b64 %0, {%1, %2};" : "=l"(r) : "f"(x), "f"(y)); return r;
}
__device__ __forceinline__ float2 unpack2(ull v) {
    float2 f; asm("mov.b64 {%0, %1}, %2;" : "=f"(f.x), "=f"(f.y) : "l"(v)); return f;
}
__device__ __forceinline__ void fma2(ull& acc, ull a, ull b) {
    asm("fma.rn.f32x2 %0, %1, %2, %3;" : "=l"(acc) : "l"(a), "l"(b), "l"(acc));
}

// ---------------------------------------------------------------------------
// K0: prep — transpose weights + zero counters
// ---------------------------------------------------------------------------
__global__ void __launch_bounds__(512)
k_prep(const float* __restrict__ w0, const float* __restrict__ w1,
       const float* __restrict__ w2, const float* __restrict__ w3,
       const float* __restrict__ w4, const float* __restrict__ w5,
       const float* __restrict__ w6, const float* __restrict__ w7) {
    int bid = blockIdx.x, t = threadIdx.x;
    if (bid < 64) {
        const float* Ws[8] = {w0, w1, w2, w3, w4, w5, w6, w7};
        int m = bid >> 3;
        int idx = (bid & 7) * 512 + t;
        float v = Ws[m][idx];
        g_Wt[m * D * D + (idx & 63) * D + (idx >> 6)] = v;
    } else {
        g_cnt[(bid - 64) * 512 + t] = 0;
    }
}

// store 4 dup-pairs {v,v} at row r, dims dd..dd+3 of a ull-format smem matrix
__device__ __forceinline__ void store_dup4(ull* row, int dd, float x, float y, float z, float w) {
    ulonglong2 a; a.x = pack2(x, x); a.y = pack2(y, y);
    ulonglong2 b; b.x = pack2(z, z); b.y = pack2(w, w);
    *(ulonglong2*)(row + dd)     = a;
    *(ulonglong2*)(row + dd + 2) = b;
}

// ---------------------------------------------------------------------------
// K1: blocks [0, NB): dsd per b.  blocks [NB, 9*NB): usu inner per (b,g).
// 128 threads. Gather: 8 rows x 16 lanes (4 dims). Matvec: 4 warp-chunks x
// 32 lanes (2 dims); inputs pre-duplicated in smem -> inner loop = LDS.64+FFMA2.
// 9th finisher per b runs finalization in place.
// ---------------------------------------------------------------------------
__global__ void __launch_bounds__(128, 7)
k_inner(const float* __restrict__ E_s, const float* __restrict__ E_d,
        const int* __restrict__ label,
        const int* __restrict__ dsd_1, const int* __restrict__ dsd_2,
        const int* __restrict__ usu_1, const int* __restrict__ usu_2,
        const int* __restrict__ usu_3, float* __restrict__ out) {
    int t = threadIdx.x;
    int g16 = t >> 4, lane = t & 15, d4 = lane * 4;
    int c4 = t >> 5, d2 = (t & 31) * 2;

    __shared__ __align__(16) ull shX[8 * XD];   // dup-pairs {x,x}
    __shared__ __align__(16) ull shY[8 * XD];
    __shared__ float shP[4][8][D];
    __shared__ float shL[4][XS];
    __shared__ int sFin;

    int b;

    if (blockIdx.x >= NB) {
        // ===================== usu inner: one (b,g) per block ================
        int bg = blockIdx.x - NB;
        b = bg >> 3;

        float4 u = make_float4(0.f, 0.f, 0.f, 0.f);
        int c2 = 0;
        if (t < 16) {
            int iu = __ldg(usu_1 + bg);
            u = *(const float4*)(E_s + iu * D + t * 4);
            int4 m0 = __ldg((const int4*)(usu_2 + bg * 8));
            int4 m1 = __ldg((const int4*)(usu_2 + bg * 8 + 4));
            c2 = (m0.x != 0) + (m0.y != 0) + (m0.z != 0) + (m0.w != 0)
               + (m1.x != 0) + (m1.y != 0) + (m1.z != 0) + (m1.w != 0);
        }

        const int4* ip = (const int4*)(usu_3 + (bg * 8 + g16) * 16);
        int4 i0 = __ldg(ip), i1 = __ldg(ip + 1), i2 = __ldg(ip + 2), i3 = __ldg(ip + 3);
        int cnt = (i0.x != 0) + (i0.y != 0) + (i0.z != 0) + (i0.w != 0)
                + (i1.x != 0) + (i1.y != 0) + (i1.z != 0) + (i1.w != 0)
                + (i2.x != 0) + (i2.y != 0) + (i2.z != 0) + (i2.w != 0)
                + (i3.x != 0) + (i3.y != 0) + (i3.z != 0) + (i3.w != 0);

        float sx = 0.f, sy = 0.f, sz = 0.f, sw = 0.f;
#define ACC(ix) { float4 v = *(const float4*)(E_s + (ix) * D + d4); \
                  sx += v.x; sy += v.y; sz += v.z; sw += v.w; }
        ACC(i0.x) ACC(i0.y) ACC(i0.z) ACC(i0.w)
        ACC(i1.x) ACC(i1.y) ACC(i1.z) ACC(i1.w)
        ACC(i2.x) ACC(i2.y) ACC(i2.z) ACC(i2.w)
        ACC(i3.x) ACC(i3.y) ACC(i3.z) ACC(i3.w)
#undef ACC
        float w = avgw(cnt);
        store_dup4(shX + g16 * XD, d4, sx * w, sy * w, sz * w, sw * w);
        __syncthreads();

        // matvec W3: warp-chunk c4 (16 e), dims d2..d2+1, 8 rows
        {
            const float* W3t = g_Wt + 4 * D * D;
            ull acc[8];
#pragma unroll
            for (int j = 0; j < 8; ++j) acc[j] = 0ull;
#pragma unroll 4
            for (int eo = 0; eo < 16; ++eo) {
                int e = c4 * 16 + eo;
                ull wv = *(const ull*)(W3t + e * D + d2);
#pragma unroll
                for (int j = 0; j < 8; ++j)
                    fma2(acc[j], shX[j * XD + e], wv);
            }
#pragma unroll
            for (int j = 0; j < 8; ++j)
                *(float2*)&shP[c4][j][d2] = unpack2(acc[j]);
        }
        __syncthreads();

        // reduce 4 chunks + leaky + pairwise j via shfl
        {
            float rx = 0.f, ry = 0.f, rz = 0.f, rw = 0.f;
#pragma unroll
            for (int c = 0; c < 4; ++c) {
                float4 p = *(float4*)&shP[c][g16][d4];
                rx += p.x; ry += p.y; rz += p.z; rw += p.w;
            }
            rx = leaky(rx); ry = leaky(ry); rz = leaky(rz); rw = leaky(rw);
            rx += __shfl_down_sync(0xffffffffu, rx, 16);
            ry += __shfl_down_sync(0xffffffffu, ry, 16);
            rz += __shfl_down_sync(0xffffffffu, rz, 16);
            rw += __shfl_down_sync(0xffffffffu, rw, 16);
            if ((t & 16) == 0)
                *(float4*)&shL[t >> 5][d4] = make_float4(rx, ry, rz, rw);
        }
        __syncthreads();

        if (t < 16) {
            int dd = t * 4;
            float Sx = 0.f, Sy = 0.f, Sz = 0.f, Sw = 0.f;
#pragma unroll
            for (int wi = 0; wi < 4; ++wi) {
                float4 l = *(float4*)&shL[wi][dd];
                Sx += l.x; Sy += l.y; Sz += l.z; Sw += l.w;
            }
            float w2 = avgw(c2);
            Sx *= w2; Sy *= w2; Sz *= w2; Sw *= w2;
            *(float4*)&g_UA[bg * D + dd] = make_float4(u.x + Sx, u.y + Sy, u.z + Sz, u.w + Sw);
            *(float4*)&g_UB[bg * D + dd] = make_float4(Sx * u.x, Sy * u.y, Sz * u.z, Sw * u.w);
            __threadfence();
        }
        __syncthreads();
    } else {
        // ===================== dsd full path: one b per block ================
        b = blockIdx.x;

        float4 td4 = make_float4(0.f, 0.f, 0.f, 0.f);
        int c1 = 0;
        if (t < 16) {
            int lb = __ldg(label + b);
            td4 = *(const float4*)(E_d + lb * D + t * 4);
            int4 m0 = __ldg((const int4*)(dsd_1 + b * 8));
            int4 m1 = __ldg((const int4*)(dsd_1 + b * 8 + 4));
            c1 = (m0.x != 0) + (m0.y != 0) + (m0.z != 0) + (m0.w != 0)
               + (m1.x != 0) + (m1.y != 0) + (m1.z != 0) + (m1.w != 0);
        }

        int ies = __ldg(dsd_1 + b * 8 + g16);
        const int4* ip = (const int4*)(dsd_2 + (b * 8 + g16) * 8);
        int4 i0 = __ldg(ip), i1 = __ldg(ip + 1);
        int cnt = (i0.x != 0) + (i0.y != 0) + (i0.z != 0) + (i0.w != 0)
                + (i1.x != 0) + (i1.y != 0) + (i1.z != 0) + (i1.w != 0);

        float4 es = *(const float4*)(E_s + ies * D + d4);
        float sx = 0.f, sy = 0.f, sz = 0.f, sw = 0.f;
#define ACC(ix) { float4 v = *(const float4*)(E_d + (ix) * D + d4); \
                  sx += v.x; sy += v.y; sz += v.z; sw += v.w; }
        ACC(i0.x) ACC(i0.y) ACC(i0.z) ACC(i0.w)
        ACC(i1.x) ACC(i1.y) ACC(i1.z) ACC(i1.w)
#undef ACC
        float w = avgw(cnt);
        float ax = sx * w, ay = sy * w, az = sz * w, aw = sw * w;
        store_dup4(shX + g16 * XD, d4, es.x + ax, es.y + ay, es.z + az, es.w + aw);
        store_dup4(shY + g16 * XD, d4, ax * es.x, ay * es.y, az * es.z, aw * es.w);
        __syncthreads();

        // hop1 dual matvec W21/W22 (warp-chunked)
        {
            const float* W21t = g_Wt + 0 * D * D;
            const float* W22t = g_Wt + 1 * D * D;
            ull acc[8];
#pragma unroll
            for (int j = 0; j < 8; ++j) acc[j] = 0ull;
#pragma unroll 4
            for (int eo = 0; eo < 16; ++eo) {
                int e = c4 * 16 + eo;
                ull wa = *(const ull*)(W21t + e * D + d2);
                ull wb = *(const ull*)(W22t + e * D + d2);
#pragma unroll
                for (int j = 0; j < 8; ++j) {
                    fma2(acc[j], shX[j * XD + e], wa);
                    fma2(acc[j], shY[j * XD + e], wb);
                }
            }
#pragma unroll
            for (int j = 0; j < 8; ++j)
                *(float2*)&shP[c4][j][d2] = unpack2(acc[j]);
        }
        __syncthreads();

        // reduce + leaky + pairwise shfl
        {
            float rx = 0.f, ry = 0.f, rz = 0.f, rw = 0.f;
#pragma unroll
            for (int c = 0; c < 4; ++c) {
                float4 p = *(float4*)&shP[c][g16][d4];
                rx += p.x; ry += p.y; rz += p.z; rw += p.w;
            }
            rx = leaky(rx); ry = leaky(ry); rz = leaky(rz); rw = leaky(rw);
            rx += __shfl_down_sync(0xffffffffu, rx, 16);
            ry += __shfl_down_sync(0xffffffffu, ry, 16);
            rz += __shfl_down_sync(0xffffffffu, rz, 16);
            rw += __shfl_down_sync(0xffffffffu, rw, 16);
            if ((t & 16) == 0)
                *(float4*)&shL[t >> 5][d4] = make_float4(rx, ry, rz, rw);
        }
        __syncthreads();

        // hop2 inputs
        if (t < 16) {
            int dd = t * 4;
            float Ax = 0.f, Ay = 0.f, Az = 0.f, Aw = 0.f;
#pragma unroll
            for (int wi = 0; wi < 4; ++wi) {
                float4 l = *(float4*)&shL[wi][dd];
                Ax += l.x; Ay += l.y; Az += l.z; Aw += l.w;
            }
            float w1 = avgw(c1);
            Ax *= w1; Ay *= w1; Az *= w1; Aw *= w1;
            store_dup4(shX, dd, Ax + td4.x, Ay + td4.y, Az + td4.z, Aw + td4.w);
            store_dup4(shY, dd, Ax * td4.x, Ay * td4.y, Az * td4.z, Aw * td4.w);
        }
        __syncthreads();

        // hop2 dual matvec W11/W12 (1 row, warp-chunked)
        {
            const float* W11t = g_Wt + 2 * D * D;
            const float* W12t = g_Wt + 3 * D * D;
            ull acc = 0ull;
#pragma unroll 4
            for (int eo = 0; eo < 16; ++eo) {
                int e = c4 * 16 + eo;
                fma2(acc, shX[e], *(const ull*)(W11t + e * D + d2));
                fma2(acc, shY[e], *(const ull*)(W12t + e * D + d2));
            }
            *(float2*)&shP[c4][0][d2] = unpack2(acc);
        }
        __syncthreads();

        if (t < 16) {
            int dd = t * 4;
            float rx = 0.f, ry = 0.f, rz = 0.f, rw = 0.f;
#pragma unroll
            for (int c = 0; c < 4; ++c) {
                float4 p = *(float4*)&shP[c][0][dd];
                rx += p.x; ry += p.y; rz += p.z; rw += p.w;
            }
            *(float4*)&g_dise[b * D + dd] =
                make_float4(leaky(rx), leaky(ry), leaky(rz), leaky(rw));
            __threadfence();
        }
        __syncthreads();
    }

    // ======================= completion + finalization =======================
    if (t == 0) {
        int old = atomicAdd(&g_cnt[b], 1);
        if (old == 8) { __threadfence(); sFin = 1; } else sFin = 0;
    }
    __syncthreads();
    if (!sFin) return;

    // --- finalization: es1 matvec + i-avg + W1u matvec + dot with dise ---
    float4 dz = make_float4(0.f, 0.f, 0.f, 0.f);
    int c1u = 0;
    if (t < 16) {
        dz = *(const float4*)&g_dise[b * D + t * 4];
        int4 m0 = __ldg((const int4*)(usu_1 + b * 8));
        int4 m1 = __ldg((const int4*)(usu_1 + b * 8 + 4));
        c1u = (m0.x != 0) + (m0.y != 0) + (m0.z != 0) + (m0.w != 0)
            + (m1.x != 0) + (m1.y != 0) + (m1.z != 0) + (m1.w != 0);
    }
    {
        float4 a = *(const float4*)&g_UA[(b * 8 + g16) * D + d4];
        float4 y = *(const float4*)&g_UB[(b * 8 + g16) * D + d4];
        store_dup4(shX + g16 * XD, d4, a.x, a.y, a.z, a.w);
        store_dup4(shY + g16 * XD, d4, y.x, y.y, y.z, y.w);
    }
    __syncthreads();

    // es1 dual matvec W21u/W22u (warp-chunked)
    {
        const float* W21t = g_Wt + 5 * D * D;
        const float* W22t = g_Wt + 6 * D * D;
        ull acc[8];
#pragma unroll
        for (int j = 0; j < 8; ++j) acc[j] = 0ull;
#pragma unroll 4
        for (int eo = 0; eo < 16; ++eo) {
            int e = c4 * 16 + eo;
            ull wa = *(const ull*)(W21t + e * D + d2);
            ull wb = *(const ull*)(W22t + e * D + d2);
#pragma unroll
            for (int j = 0; j < 8; ++j) {
                fma2(acc[j], shX[j * XD + e], wa);
                fma2(acc[j], shY[j * XD + e], wb);
            }
        }
#pragma unroll
        for (int j = 0; j < 8; ++j)
            *(float2*)&shP[c4][j][d2] = unpack2(acc[j]);
    }
    __syncthreads();

    // reduce + leaky + pairwise shfl
    {
        float rx = 0.f, ry = 0.f, rz = 0.f, rw = 0.f;
#pragma unroll
        for (int c = 0; c < 4; ++c) {
            float4 p = *(float4*)&shP[c][g16][d4];
            rx += p.x; ry += p.y; rz += p.z; rw += p.w;
        }
        rx = leaky(rx); ry = leaky(ry); rz = leaky(rz); rw = leaky(rw);
        rx += __shfl_down_sync(0xffffffffu, rx, 16);
        ry += __shfl_down_sync(0xffffffffu, ry, 16);
        rz += __shfl_down_sync(0xffffffffu, rz, 16);
        rw += __shfl_down_sync(0xffffffffu, rw, 16);
        if ((t & 16) == 0)
            *(float4*)&shL[t >> 5][d4] = make_float4(rx, ry, rz, rw);
    }
    __syncthreads();

    // i-avg
    if (t < 16) {
        int dd = t * 4;
        float Tx = 0.f, Ty = 0.f, Tz = 0.f, Tw = 0.f;
#pragma unroll
        for (int wi = 0; wi < 4; ++wi) {
            float4 l = *(float4*)&shL[wi][dd];
            Tx += l.x; Ty += l.y; Tz += l.z; Tw += l.w;
        }
        float w1 = avgw(c1u);
        store_dup4(shX, dd, Tx * w1, Ty * w1, Tz * w1, Tw * w1);
    }
    __syncthreads();

    // emb_user matvec W1u (1 row, warp-chunked)
    {
        const float* W1t = g_Wt + 7 * D * D;
        ull acc = 0ull;
#pragma unroll 4
        for (int eo = 0; eo < 16; ++eo) {
            int e = c4 * 16 + eo;
            fma2(acc, shX[e], *(const ull*)(W1t + e * D + d2));
        }
        *(float2*)&shP[c4][0][d2] = unpack2(acc);
    }
    __syncthreads();

    // final reduce + dot with emb_dise
    if (t < 16) {
        int dd = t * 4;
        float rx = 0.f, ry = 0.f, rz = 0.f, rw = 0.f;
#pragma unroll
        for (int c = 0; c < 4; ++c) {
            float4 p = *(float4*)&shP[c][0][dd];
            rx += p.x; ry += p.y; rz += p.z; rw += p.w;
        }
        float v = leaky(rx) * dz.x + leaky(ry) * dz.y +
                  leaky(rz) * dz.z + leaky(rw) * dz.w;
        v += __shfl_down_sync(0x0000ffffu, v, 8, 16);
        v += __shfl_down_sync(0x0000ffffu, v, 4, 16);
        v += __shfl_down_sync(0x0000ffffu, v, 2, 16);
        v += __shfl_down_sync(0x0000ffffu, v, 1, 16);
        if (t == 0) out[b] = v;
    }
}

// ---------------------------------------------------------------------------
extern "C" void kernel_launch(void* const* d_in, const int* in_sizes, int n_in,
                              void* d_out, int out_size) {
    const float* E_s = (const float*)d_in[0];
    const float* E_d = (const float*)d_in[1];
    // weights: W_dsd_21, W_dsd_22, W_dsd_11, W_dsd_12, W_usu_3, W_usu_21, W_usu_22, W_usu_1
    k_prep<<<66, 512>>>((const float*)d_in[2], (const float*)d_in[3],
                        (const float*)d_in[4], (const float*)d_in[5],
                        (const float*)d_in[6], (const float*)d_in[7],
                        (const float*)d_in[8], (const float*)d_in[9]);

    k_inner<<<NB * 9, 128>>>(E_s, E_d,
                             (const int*)d_in[10], (const int*)d_in[11],
                             (const int*)d_in[12], (const int*)d_in[13],
                             (const int*)d_in[14], (const int*)d_in[15],
                             (float*)d_out);
}

// round 9
// speedup vs baseline: 1.0324x; 1.0324x over previous
#include <cuda_runtime.h>

#define D 64
#define NB 1024
#define XS 68   // float smem row stride
#define XD 66   // ull smem row stride (528B, 16B-aligned)

// Scratch (allocation-free rule: __device__ globals)
__device__ __align__(16) float g_Wt[8 * D * D];    // Wt[m][e*64+d] = W[m][d*64+e]
__device__ __align__(16) float g_UA[NB * 8 * D];   // u1 + S
__device__ __align__(16) float g_UB[NB * 8 * D];   // S * u1
__device__ __align__(16) float g_dise[NB * D];     // emb_dise
__device__ int g_cnt[NB];                          // completion counters

typedef unsigned long long ull;

__device__ __forceinline__ float leaky(float x) { return fmaxf(x, 0.2f * x); }
__device__ __forceinline__ float avgw(int cnt)  { return cnt > 0 ? 1.0f / ((float)cnt + 1e-8f) : 0.0f; }

__device__ __forceinline__ ull pack2(float x, float y) {
    ull r; asm("mov.b64 %0, {%1, %2};" : "=l"(r) : "f"(x), "f"(y)); return r;
}
__device__ __forceinline__ float2 unpack2(ull v) {
    float2 f; asm("mov.b64 {%0, %1}, %2;" : "=f"(f.x), "=f"(f.y) : "l"(v)); return f;
}
__device__ __forceinline__ void fma2(ull& acc, ull a, ull b) {
    asm("fma.rn.f32x2 %0, %1, %2, %3;" : "=l"(acc) : "l"(a), "l"(b), "l"(acc));
}

// ---------------------------------------------------------------------------
// K0: prep — transpose weights + zero counters
// ---------------------------------------------------------------------------
__global__ void __launch_bounds__(512)
k_prep(const float* __restrict__ w0, const float* __restrict__ w1,
       const float* __restrict__ w2, const float* __restrict__ w3,
       const float* __restrict__ w4, const float* __restrict__ w5,
       const float* __restrict__ w6, const float* __restrict__ w7) {
    int bid = blockIdx.x, t = threadIdx.x;
    if (bid < 64) {
        const float* Ws[8] = {w0, w1, w2, w3, w4, w5, w6, w7};
        int m = bid >> 3;
        int idx = (bid & 7) * 512 + t;
        float v = Ws[m][idx];
        g_Wt[m * D * D + (idx & 63) * D + (idx >> 6)] = v;
    } else {
        g_cnt[(bid - 64) * 512 + t] = 0;
    }
}

// store 4 dup-pairs {v,v} at dims dd..dd+3 of a ull-format smem row
__device__ __forceinline__ void store_dup4(ull* row, int dd, float x, float y, float z, float w) {
    ulonglong2 a; a.x = pack2(x, x); a.y = pack2(y, y);
    ulonglong2 b; b.x = pack2(z, z); b.y = pack2(w, w);
    *(ulonglong2*)(row + dd)     = a;
    *(ulonglong2*)(row + dd + 2) = b;
}

// ---------------------------------------------------------------------------
// K1: blocks [0, NB): dsd per b.  blocks [NB, 9*NB): usu inner per (b,g).
// 128 threads. Gather: 8 rows x 16 lanes (4 dims). Matvec: 4 warp-chunks x
// 32 lanes (2 dims); inputs as dup-pairs, read 2 e-values per LDS.128.
// 9th finisher per b runs finalization in place.
// ---------------------------------------------------------------------------
__global__ void __launch_bounds__(128, 7)
k_inner(const float* __restrict__ E_s, const float* __restrict__ E_d,
        const int* __restrict__ label,
        const int* __restrict__ dsd_1, const int* __restrict__ dsd_2,
        const int* __restrict__ usu_1, const int* __restrict__ usu_2,
        const int* __restrict__ usu_3, float* __restrict__ out) {
    int t = threadIdx.x;
    int g16 = t >> 4, lane = t & 15, d4 = lane * 4;
    int c4 = t >> 5, d2 = (t & 31) * 2;

    __shared__ __align__(16) ull shX[8 * XD];   // dup-pairs {x,x}
    __shared__ __align__(16) ull shY[8 * XD];
    __shared__ float shP[4][8][D];
    __shared__ float shL[4][XS];
    __shared__ int sFin;

    int b;

    if (blockIdx.x >= NB) {
        // ===================== usu inner: one (b,g) per block ================
        int bg = blockIdx.x - NB;
        b = bg >> 3;

        float4 u = make_float4(0.f, 0.f, 0.f, 0.f);
        int c2 = 0;
        if (t < 16) {
            int iu = __ldg(usu_1 + bg);
            u = *(const float4*)(E_s + iu * D + t * 4);
            int4 m0 = __ldg((const int4*)(usu_2 + bg * 8));
            int4 m1 = __ldg((const int4*)(usu_2 + bg * 8 + 4));
            c2 = (m0.x != 0) + (m0.y != 0) + (m0.z != 0) + (m0.w != 0)
               + (m1.x != 0) + (m1.y != 0) + (m1.z != 0) + (m1.w != 0);
        }

        const int4* ip = (const int4*)(usu_3 + (bg * 8 + g16) * 16);
        int4 i0 = __ldg(ip), i1 = __ldg(ip + 1), i2 = __ldg(ip + 2), i3 = __ldg(ip + 3);
        int cnt = (i0.x != 0) + (i0.y != 0) + (i0.z != 0) + (i0.w != 0)
                + (i1.x != 0) + (i1.y != 0) + (i1.z != 0) + (i1.w != 0)
                + (i2.x != 0) + (i2.y != 0) + (i2.z != 0) + (i2.w != 0)
                + (i3.x != 0) + (i3.y != 0) + (i3.z != 0) + (i3.w != 0);

        float sx = 0.f, sy = 0.f, sz = 0.f, sw = 0.f;
#define ACC(ix) { float4 v = *(const float4*)(E_s + (ix) * D + d4); \
                  sx += v.x; sy += v.y; sz += v.z; sw += v.w; }
        ACC(i0.x) ACC(i0.y) ACC(i0.z) ACC(i0.w)
        ACC(i1.x) ACC(i1.y) ACC(i1.z) ACC(i1.w)
        ACC(i2.x) ACC(i2.y) ACC(i2.z) ACC(i2.w)
        ACC(i3.x) ACC(i3.y) ACC(i3.z) ACC(i3.w)
#undef ACC
        float w = avgw(cnt);
        store_dup4(shX + g16 * XD, d4, sx * w, sy * w, sz * w, sw * w);
        __syncthreads();

        // matvec W3: warp-chunk c4 (16 e = 8 pairs), dims d2..d2+1, 8 rows
        {
            const float* W3t = g_Wt + 4 * D * D;
            ull acc[8];
#pragma unroll
            for (int j = 0; j < 8; ++j) acc[j] = 0ull;
#pragma unroll
            for (int ep = 0; ep < 8; ++ep) {
                int e = c4 * 16 + ep * 2;
                ull w0 = *(const ull*)(W3t + e * D + d2);
                ull w1 = *(const ull*)(W3t + e * D + D + d2);
#pragma unroll
                for (int j = 0; j < 8; ++j) {
                    ulonglong2 xx = *(const ulonglong2*)(shX + j * XD + e);
                    fma2(acc[j], xx.x, w0);
                    fma2(acc[j], xx.y, w1);
                }
            }
#pragma unroll
            for (int j = 0; j < 8; ++j)
                *(float2*)&shP[c4][j][d2] = unpack2(acc[j]);
        }
        __syncthreads();

        // reduce 4 chunks + leaky + pairwise j via shfl
        {
            float rx = 0.f, ry = 0.f, rz = 0.f, rw = 0.f;
#pragma unroll
            for (int c = 0; c < 4; ++c) {
                float4 p = *(float4*)&shP[c][g16][d4];
                rx += p.x; ry += p.y; rz += p.z; rw += p.w;
            }
            rx = leaky(rx); ry = leaky(ry); rz = leaky(rz); rw = leaky(rw);
            rx += __shfl_down_sync(0xffffffffu, rx, 16);
            ry += __shfl_down_sync(0xffffffffu, ry, 16);
            rz += __shfl_down_sync(0xffffffffu, rz, 16);
            rw += __shfl_down_sync(0xffffffffu, rw, 16);
            if ((t & 16) == 0)
                *(float4*)&shL[t >> 5][d4] = make_float4(rx, ry, rz, rw);
        }
        __syncthreads();

        if (t < 16) {
            int dd = t * 4;
            float Sx = 0.f, Sy = 0.f, Sz = 0.f, Sw = 0.f;
#pragma unroll
            for (int wi = 0; wi < 4; ++wi) {
                float4 l = *(float4*)&shL[wi][dd];
                Sx += l.x; Sy += l.y; Sz += l.z; Sw += l.w;
            }
            float w2 = avgw(c2);
            Sx *= w2; Sy *= w2; Sz *= w2; Sw *= w2;
            *(float4*)&g_UA[bg * D + dd] = make_float4(u.x + Sx, u.y + Sy, u.z + Sz, u.w + Sw);
            *(float4*)&g_UB[bg * D + dd] = make_float4(Sx * u.x, Sy * u.y, Sz * u.z, Sw * u.w);
            __threadfence();
        }
        __syncthreads();
    } else {
        // ===================== dsd full path: one b per block ================
        b = blockIdx.x;

        float4 td4 = make_float4(0.f, 0.f, 0.f, 0.f);
        int c1 = 0;
        if (t < 16) {
            int lb = __ldg(label + b);
            td4 = *(const float4*)(E_d + lb * D + t * 4);
            int4 m0 = __ldg((const int4*)(dsd_1 + b * 8));
            int4 m1 = __ldg((const int4*)(dsd_1 + b * 8 + 4));
            c1 = (m0.x != 0) + (m0.y != 0) + (m0.z != 0) + (m0.w != 0)
               + (m1.x != 0) + (m1.y != 0) + (m1.z != 0) + (m1.w != 0);
        }

        int ies = __ldg(dsd_1 + b * 8 + g16);
        const int4* ip = (const int4*)(dsd_2 + (b * 8 + g16) * 8);
        int4 i0 = __ldg(ip), i1 = __ldg(ip + 1);
        int cnt = (i0.x != 0) + (i0.y != 0) + (i0.z != 0) + (i0.w != 0)
                + (i1.x != 0) + (i1.y != 0) + (i1.z != 0) + (i1.w != 0);

        float4 es = *(const float4*)(E_s + ies * D + d4);
        float sx = 0.f, sy = 0.f, sz = 0.f, sw = 0.f;
#define ACC(ix) { float4 v = *(const float4*)(E_d + (ix) * D + d4); \
                  sx += v.x; sy += v.y; sz += v.z; sw += v.w; }
        ACC(i0.x) ACC(i0.y) ACC(i0.z) ACC(i0.w)
        ACC(i1.x) ACC(i1.y) ACC(i1.z) ACC(i1.w)
#undef ACC
        float w = avgw(cnt);
        float ax = sx * w, ay = sy * w, az = sz * w, aw = sw * w;
        store_dup4(shX + g16 * XD, d4, es.x + ax, es.y + ay, es.z + az, es.w + aw);
        store_dup4(shY + g16 * XD, d4, ax * es.x, ay * es.y, az * es.z, aw * es.w);
        __syncthreads();

        // hop1 dual matvec W21/W22 (warp-chunked, e-paired)
        {
            const float* W21t = g_Wt + 0 * D * D;
            const float* W22t = g_Wt + 1 * D * D;
            ull acc[8];
#pragma unroll
            for (int j = 0; j < 8; ++j) acc[j] = 0ull;
#pragma unroll
            for (int ep = 0; ep < 8; ++ep) {
                int e = c4 * 16 + ep * 2;
                ull wa0 = *(const ull*)(W21t + e * D + d2);
                ull wa1 = *(const ull*)(W21t + e * D + D + d2);
                ull wb0 = *(const ull*)(W22t + e * D + d2);
                ull wb1 = *(const ull*)(W22t + e * D + D + d2);
#pragma unroll
                for (int j = 0; j < 8; ++j) {
                    ulonglong2 xx = *(const ulonglong2*)(shX + j * XD + e);
                    ulonglong2 yy = *(const ulonglong2*)(shY + j * XD + e);
                    fma2(acc[j], xx.x, wa0);
                    fma2(acc[j], xx.y, wa1);
                    fma2(acc[j], yy.x, wb0);
                    fma2(acc[j], yy.y, wb1);
                }
            }
#pragma unroll
            for (int j = 0; j < 8; ++j)
                *(float2*)&shP[c4][j][d2] = unpack2(acc[j]);
        }
        __syncthreads();

        // reduce + leaky + pairwise shfl
        {
            float rx = 0.f, ry = 0.f, rz = 0.f, rw = 0.f;
#pragma unroll
            for (int c = 0; c < 4; ++c) {
                float4 p = *(float4*)&shP[c][g16][d4];
                rx += p.x; ry += p.y; rz += p.z; rw += p.w;
            }
            rx = leaky(rx); ry = leaky(ry); rz = leaky(rz); rw = leaky(rw);
            rx += __shfl_down_sync(0xffffffffu, rx, 16);
            ry += __shfl_down_sync(0xffffffffu, ry, 16);
            rz += __shfl_down_sync(0xffffffffu, rz, 16);
            rw += __shfl_down_sync(0xffffffffu, rw, 16);
            if ((t & 16) == 0)
                *(float4*)&shL[t >> 5][d4] = make_float4(rx, ry, rz, rw);
        }
        __syncthreads();

        // hop2 inputs
        if (t < 16) {
            int dd = t * 4;
            float Ax = 0.f, Ay = 0.f, Az = 0.f, Aw = 0.f;
#pragma unroll
            for (int wi = 0; wi < 4; ++wi) {
                float4 l = *(float4*)&shL[wi][dd];
                Ax += l.x; Ay += l.y; Az += l.z; Aw += l.w;
            }
            float w1 = avgw(c1);
            Ax *= w1; Ay *= w1; Az *= w1; Aw *= w1;
            store_dup4(shX, dd, Ax + td4.x, Ay + td4.y, Az + td4.z, Aw + td4.w);
            store_dup4(shY, dd, Ax * td4.x, Ay * td4.y, Az * td4.z, Aw * td4.w);
        }
        __syncthreads();

        // hop2 dual matvec W11/W12 (1 row, e-paired)
        {
            const float* W11t = g_Wt + 2 * D * D;
            const float* W12t = g_Wt + 3 * D * D;
            ull acc = 0ull;
#pragma unroll
            for (int ep = 0; ep < 8; ++ep) {
                int e = c4 * 16 + ep * 2;
                ulonglong2 xx = *(const ulonglong2*)(shX + e);
                ulonglong2 yy = *(const ulonglong2*)(shY + e);
                fma2(acc, xx.x, *(const ull*)(W11t + e * D + d2));
                fma2(acc, xx.y, *(const ull*)(W11t + e * D + D + d2));
                fma2(acc, yy.x, *(const ull*)(W12t + e * D + d2));
                fma2(acc, yy.y, *(const ull*)(W12t + e * D + D + d2));
            }
            *(float2*)&shP[c4][0][d2] = unpack2(acc);
        }
        __syncthreads();

        if (t < 16) {
            int dd = t * 4;
            float rx = 0.f, ry = 0.f, rz = 0.f, rw = 0.f;
#pragma unroll
            for (int c = 0; c < 4; ++c) {
                float4 p = *(float4*)&shP[c][0][dd];
                rx += p.x; ry += p.y; rz += p.z; rw += p.w;
            }
            *(float4*)&g_dise[b * D + dd] =
                make_float4(leaky(rx), leaky(ry), leaky(rz), leaky(rw));
            __threadfence();
        }
        __syncthreads();
    }

    // ======================= completion + finalization =======================
    if (t == 0) {
        int old = atomicAdd(&g_cnt[b], 1);
        if (old == 8) { __threadfence(); sFin = 1; } else sFin = 0;
    }
    __syncthreads();
    if (!sFin) return;

    // --- finalization: es1 matvec + i-avg + W1u matvec + dot with dise ---
    float4 dz = make_float4(0.f, 0.f, 0.f, 0.f);
    int c1u = 0;
    if (t < 16) {
        dz = *(const float4*)&g_dise[b * D + t * 4];
        int4 m0 = __ldg((const int4*)(usu_1 + b * 8));
        int4 m1 = __ldg((const int4*)(usu_1 + b * 8 + 4));
        c1u = (m0.x != 0) + (m0.y != 0) + (m0.z != 0) + (m0.w != 0)
            + (m1.x != 0) + (m1.y != 0) + (m1.z != 0) + (m1.w != 0);
    }
    {
        float4 a = *(const float4*)&g_UA[(b * 8 + g16) * D + d4];
        float4 y = *(const float4*)&g_UB[(b * 8 + g16) * D + d4];
        store_dup4(shX + g16 * XD, d4, a.x, a.y, a.z, a.w);
        store_dup4(shY + g16 * XD, d4, y.x, y.y, y.z, y.w);
    }
    __syncthreads();

    // es1 dual matvec W21u/W22u (warp-chunked, e-paired)
    {
        const float* W21t = g_Wt + 5 * D * D;
        const float* W22t = g_Wt + 6 * D * D;
        ull acc[8];
#pragma unroll
        for (int j = 0; j < 8; ++j) acc[j] = 0ull;
#pragma unroll
        for (int ep = 0; ep < 8; ++ep) {
            int e = c4 * 16 + ep * 2;
            ull wa0 = *(const ull*)(W21t + e * D + d2);
            ull wa1 = *(const ull*)(W21t + e * D + D + d2);
            ull wb0 = *(const ull*)(W22t + e * D + d2);
            ull wb1 = *(const ull*)(W22t + e * D + D + d2);
#pragma unroll
            for (int j = 0; j < 8; ++j) {
                ulonglong2 xx = *(const ulonglong2*)(shX + j * XD + e);
                ulonglong2 yy = *(const ulonglong2*)(shY + j * XD + e);
                fma2(acc[j], xx.x, wa0);
                fma2(acc[j], xx.y, wa1);
                fma2(acc[j], yy.x, wb0);
                fma2(acc[j], yy.y, wb1);
            }
        }
#pragma unroll
        for (int j = 0; j < 8; ++j)
            *(float2*)&shP[c4][j][d2] = unpack2(acc[j]);
    }
    __syncthreads();

    // reduce + leaky + pairwise shfl
    {
        float rx = 0.f, ry = 0.f, rz = 0.f, rw = 0.f;
#pragma unroll
        for (int c = 0; c < 4; ++c) {
            float4 p = *(float4*)&shP[c][g16][d4];
            rx += p.x; ry += p.y; rz += p.z; rw += p.w;
        }
        rx = leaky(rx); ry = leaky(ry); rz = leaky(rz); rw = leaky(rw);
        rx += __shfl_down_sync(0xffffffffu, rx, 16);
        ry += __shfl_down_sync(0xffffffffu, ry, 16);
        rz += __shfl_down_sync(0xffffffffu, rz, 16);
        rw += __shfl_down_sync(0xffffffffu, rw, 16);
        if ((t & 16) == 0)
            *(float4*)&shL[t >> 5][d4] = make_float4(rx, ry, rz, rw);
    }
    __syncthreads();

    // i-avg
    if (t < 16) {
        int dd = t * 4;
        float Tx = 0.f, Ty = 0.f, Tz = 0.f, Tw = 0.f;
#pragma unroll
        for (int wi = 0; wi < 4; ++wi) {
            float4 l = *(float4*)&shL[wi][dd];
            Tx += l.x; Ty += l.y; Tz += l.z; Tw += l.w;
        }
        float w1 = avgw(c1u);
        store_dup4(shX, dd, Tx * w1, Ty * w1, Tz * w1, Tw * w1);
    }
    __syncthreads();

    // emb_user matvec W1u (1 row, e-paired)
    {
        const float* W1t = g_Wt + 7 * D * D;
        ull acc = 0ull;
#pragma unroll
        for (int ep = 0; ep < 8; ++ep) {
            int e = c4 * 16 + ep * 2;
            ulonglong2 xx = *(const ulonglong2*)(shX + e);
            fma2(acc, xx.x, *(const ull*)(W1t + e * D + d2));
            fma2(acc, xx.y, *(const ull*)(W1t + e * D + D + d2));
        }
        *(float2*)&shP[c4][0][d2] = unpack2(acc);
    }
    __syncthreads();

    // final reduce + dot with emb_dise
    if (t < 16) {
        int dd = t * 4;
        float rx = 0.f, ry = 0.f, rz = 0.f, rw = 0.f;
#pragma unroll
        for (int c = 0; c < 4; ++c) {
            float4 p = *(float4*)&shP[c][0][dd];
            rx += p.x; ry += p.y; rz += p.z; rw += p.w;
        }
        float v = leaky(rx) * dz.x + leaky(ry) * dz.y +
                  leaky(rz) * dz.z + leaky(rw) * dz.w;
        v += __shfl_down_sync(0x0000ffffu, v, 8, 16);
        v += __shfl_down_sync(0x0000ffffu, v, 4, 16);
        v += __shfl_down_sync(0x0000ffffu, v, 2, 16);
        v += __shfl_down_sync(0x0000ffffu, v, 1, 16);
        if (t == 0) out[b] = v;
    }
}

// ---------------------------------------------------------------------------
extern "C" void kernel_launch(void* const* d_in, const int* in_sizes, int n_in,
                              void* d_out, int out_size) {
    const float* E_s = (const float*)d_in[0];
    const float* E_d = (const float*)d_in[1];
    // weights: W_dsd_21, W_dsd_22, W_dsd_11, W_dsd_12, W_usu_3, W_usu_21, W_usu_22, W_usu_1
    k_prep<<<66, 512>>>((const float*)d_in[2], (const float*)d_in[3],
                        (const float*)d_in[4], (const float*)d_in[5],
                        (const float*)d_in[6], (const float*)d_in[7],
                        (const float*)d_in[8], (const float*)d_in[9]);

    k_inner<<<NB * 9, 128>>>(E_s, E_d,
                             (const int*)d_in[10], (const int*)d_in[11],
                             (const int*)d_in[12], (const int*)d_in[13],
                             (const int*)d_in[14], (const int*)d_in[15],
                             (float*)d_out);
}

// round 10
// speedup vs baseline: 1.1422x; 1.1064x over previous
#include <cuda_runtime.h>

#define D 64
#define NB 1024
#define XS 68   // float smem row stride (272B, 16B-aligned)

// Scratch (allocation-free rule: __device__ globals)
__device__ __align__(16) float g_Wt[8 * D * D];    // Wt[m][e*64+d] = W[m][d*64+e]
__device__ __align__(16) float g_UA[NB * 8 * D];   // u1 + S
__device__ __align__(16) float g_UB[NB * 8 * D];   // S * u1
__device__ __align__(16) float g_dise[NB * D];     // emb_dise
__device__ int g_cnt[NB];                          // completion counters

typedef unsigned long long ull;

__device__ __forceinline__ float leaky(float x) { return fmaxf(x, 0.2f * x); }
__device__ __forceinline__ float avgw(int cnt)  { return cnt > 0 ? 1.0f / ((float)cnt + 1e-8f) : 0.0f; }

__device__ __forceinline__ ull pack2(float x, float y) {
    ull r; asm("mov.b64 %0, {%1, %2};" : "=l"(r) : "f"(x), "f"(y)); return r;
}
__device__ __forceinline__ float2 unpack2(ull v) {
    float2 f; asm("mov.b64 {%0, %1}, %2;" : "=f"(f.x), "=f"(f.y) : "l"(v)); return f;
}
__device__ __forceinline__ void fma2(ull& acc, ull a, ull b) {
    asm("fma.rn.f32x2 %0, %1, %2, %3;" : "=l"(acc) : "l"(a), "l"(b), "l"(acc));
}

// ---------------------------------------------------------------------------
// K0: prep — transpose weights + zero counters
// ---------------------------------------------------------------------------
__global__ void __launch_bounds__(512)
k_prep(const float* __restrict__ w0, const float* __restrict__ w1,
       const float* __restrict__ w2, const float* __restrict__ w3,
       const float* __restrict__ w4, const float* __restrict__ w5,
       const float* __restrict__ w6, const float* __restrict__ w7) {
    int bid = blockIdx.x, t = threadIdx.x;
    if (bid < 64) {
        const float* Ws[8] = {w0, w1, w2, w3, w4, w5, w6, w7};
        int m = bid >> 3;
        int idx = (bid & 7) * 512 + t;
        float v = Ws[m][idx];
        g_Wt[m * D * D + (idx & 63) * D + (idx >> 6)] = v;
    } else {
        g_cnt[(bid - 64) * 512 + t] = 0;
    }
}

// ---------------------------------------------------------------------------
// K1: blocks [0, NB): dsd per b.  blocks [NB, 9*NB): usu inner per (b,g).
// 128 threads. Gather: 8 rows x 16 lanes (4 dims). Matvec: 4 warp-chunks x
// 32 lanes (2 dims); x read as float4 (1 LDS.128 = 4 e), dup-pairs built in
// registers (ALU) to keep the L1 pipe free. 9th finisher per b finalizes.
// ---------------------------------------------------------------------------
__global__ void __launch_bounds__(128, 7)
k_inner(const float* __restrict__ E_s, const float* __restrict__ E_d,
        const int* __restrict__ label,
        const int* __restrict__ dsd_1, const int* __restrict__ dsd_2,
        const int* __restrict__ usu_1, const int* __restrict__ usu_2,
        const int* __restrict__ usu_3, float* __restrict__ out) {
    int t = threadIdx.x;
    int g16 = t >> 4, lane = t & 15, d4 = lane * 4;
    int c4 = t >> 5, d2 = (t & 31) * 2;

    __shared__ __align__(16) float shX[8 * XS];
    __shared__ __align__(16) float shY[8 * XS];
    __shared__ float shP[4][8][D];
    __shared__ float shL[4][XS];
    __shared__ int sFin;

    int b;

    if (blockIdx.x >= NB) {
        // ===================== usu inner: one (b,g) per block ================
        int bg = blockIdx.x - NB;
        b = bg >> 3;

        float4 u = make_float4(0.f, 0.f, 0.f, 0.f);
        int c2 = 0;
        if (t < 16) {
            int iu = __ldg(usu_1 + bg);
            u = *(const float4*)(E_s + iu * D + t * 4);
            int4 m0 = __ldg((const int4*)(usu_2 + bg * 8));
            int4 m1 = __ldg((const int4*)(usu_2 + bg * 8 + 4));
            c2 = (m0.x != 0) + (m0.y != 0) + (m0.z != 0) + (m0.w != 0)
               + (m1.x != 0) + (m1.y != 0) + (m1.z != 0) + (m1.w != 0);
        }

        const int4* ip = (const int4*)(usu_3 + (bg * 8 + g16) * 16);
        int4 i0 = __ldg(ip), i1 = __ldg(ip + 1), i2 = __ldg(ip + 2), i3 = __ldg(ip + 3);
        int cnt = (i0.x != 0) + (i0.y != 0) + (i0.z != 0) + (i0.w != 0)
                + (i1.x != 0) + (i1.y != 0) + (i1.z != 0) + (i1.w != 0)
                + (i2.x != 0) + (i2.y != 0) + (i2.z != 0) + (i2.w != 0)
                + (i3.x != 0) + (i3.y != 0) + (i3.z != 0) + (i3.w != 0);

        float sx = 0.f, sy = 0.f, sz = 0.f, sw = 0.f;
#define ACC(ix) { float4 v = *(const float4*)(E_s + (ix) * D + d4); \
                  sx += v.x; sy += v.y; sz += v.z; sw += v.w; }
        ACC(i0.x) ACC(i0.y) ACC(i0.z) ACC(i0.w)
        ACC(i1.x) ACC(i1.y) ACC(i1.z) ACC(i1.w)
        ACC(i2.x) ACC(i2.y) ACC(i2.z) ACC(i2.w)
        ACC(i3.x) ACC(i3.y) ACC(i3.z) ACC(i3.w)
#undef ACC
        float w = avgw(cnt);
        *(float4*)&shX[g16 * XS + d4] = make_float4(sx * w, sy * w, sz * w, sw * w);
        __syncthreads();

        // matvec W3: warp-chunk c4 (16 e = 4 quads), dims d2..d2+1, 8 rows
        {
            const float* W3t = g_Wt + 4 * D * D;
            ull acc[8];
#pragma unroll
            for (int j = 0; j < 8; ++j) acc[j] = 0ull;
#pragma unroll
            for (int ep = 0; ep < 4; ++ep) {
                int e = c4 * 16 + ep * 4;
                ull w0 = *(const ull*)(W3t + (e + 0) * D + d2);
                ull w1 = *(const ull*)(W3t + (e + 1) * D + d2);
                ull w2 = *(const ull*)(W3t + (e + 2) * D + d2);
                ull w3 = *(const ull*)(W3t + (e + 3) * D + d2);
#pragma unroll
                for (int j = 0; j < 8; ++j) {
                    float4 xv = *(const float4*)&shX[j * XS + e];
                    fma2(acc[j], pack2(xv.x, xv.x), w0);
                    fma2(acc[j], pack2(xv.y, xv.y), w1);
                    fma2(acc[j], pack2(xv.z, xv.z), w2);
                    fma2(acc[j], pack2(xv.w, xv.w), w3);
                }
            }
#pragma unroll
            for (int j = 0; j < 8; ++j)
                *(float2*)&shP[c4][j][d2] = unpack2(acc[j]);
        }
        __syncthreads();

        // reduce 4 chunks + leaky + pairwise j via shfl
        {
            float rx = 0.f, ry = 0.f, rz = 0.f, rw = 0.f;
#pragma unroll
            for (int c = 0; c < 4; ++c) {
                float4 p = *(float4*)&shP[c][g16][d4];
                rx += p.x; ry += p.y; rz += p.z; rw += p.w;
            }
            rx = leaky(rx); ry = leaky(ry); rz = leaky(rz); rw = leaky(rw);
            rx += __shfl_down_sync(0xffffffffu, rx, 16);
            ry += __shfl_down_sync(0xffffffffu, ry, 16);
            rz += __shfl_down_sync(0xffffffffu, rz, 16);
            rw += __shfl_down_sync(0xffffffffu, rw, 16);
            if ((t & 16) == 0)
                *(float4*)&shL[t >> 5][d4] = make_float4(rx, ry, rz, rw);
        }
        __syncthreads();

        if (t < 16) {
            int dd = t * 4;
            float Sx = 0.f, Sy = 0.f, Sz = 0.f, Sw = 0.f;
#pragma unroll
            for (int wi = 0; wi < 4; ++wi) {
                float4 l = *(float4*)&shL[wi][dd];
                Sx += l.x; Sy += l.y; Sz += l.z; Sw += l.w;
            }
            float w2 = avgw(c2);
            Sx *= w2; Sy *= w2; Sz *= w2; Sw *= w2;
            *(float4*)&g_UA[bg * D + dd] = make_float4(u.x + Sx, u.y + Sy, u.z + Sz, u.w + Sw);
            *(float4*)&g_UB[bg * D + dd] = make_float4(Sx * u.x, Sy * u.y, Sz * u.z, Sw * u.w);
            __threadfence();
        }
        __syncthreads();
    } else {
        // ===================== dsd full path: one b per block ================
        b = blockIdx.x;

        float4 td4 = make_float4(0.f, 0.f, 0.f, 0.f);
        int c1 = 0;
        if (t < 16) {
            int lb = __ldg(label + b);
            td4 = *(const float4*)(E_d + lb * D + t * 4);
            int4 m0 = __ldg((const int4*)(dsd_1 + b * 8));
            int4 m1 = __ldg((const int4*)(dsd_1 + b * 8 + 4));
            c1 = (m0.x != 0) + (m0.y != 0) + (m0.z != 0) + (m0.w != 0)
               + (m1.x != 0) + (m1.y != 0) + (m1.z != 0) + (m1.w != 0);
        }

        int ies = __ldg(dsd_1 + b * 8 + g16);
        const int4* ip = (const int4*)(dsd_2 + (b * 8 + g16) * 8);
        int4 i0 = __ldg(ip), i1 = __ldg(ip + 1);
        int cnt = (i0.x != 0) + (i0.y != 0) + (i0.z != 0) + (i0.w != 0)
                + (i1.x != 0) + (i1.y != 0) + (i1.z != 0) + (i1.w != 0);

        float4 es = *(const float4*)(E_s + ies * D + d4);
        float sx = 0.f, sy = 0.f, sz = 0.f, sw = 0.f;
#define ACC(ix) { float4 v = *(const float4*)(E_d + (ix) * D + d4); \
                  sx += v.x; sy += v.y; sz += v.z; sw += v.w; }
        ACC(i0.x) ACC(i0.y) ACC(i0.z) ACC(i0.w)
        ACC(i1.x) ACC(i1.y) ACC(i1.z) ACC(i1.w)
#undef ACC
        float w = avgw(cnt);
        float ax = sx * w, ay = sy * w, az = sz * w, aw = sw * w;
        *(float4*)&shX[g16 * XS + d4] = make_float4(es.x + ax, es.y + ay, es.z + az, es.w + aw);
        *(float4*)&shY[g16 * XS + d4] = make_float4(ax * es.x, ay * es.y, az * es.z, aw * es.w);
        __syncthreads();

        // hop1 dual matvec W21/W22 (warp-chunked, float4 x + reg dup)
        {
            const float* W21t = g_Wt + 0 * D * D;
            const float* W22t = g_Wt + 1 * D * D;
            ull acc[8];
#pragma unroll
            for (int j = 0; j < 8; ++j) acc[j] = 0ull;
#pragma unroll
            for (int ep = 0; ep < 4; ++ep) {
                int e = c4 * 16 + ep * 4;
                ull wa0 = *(const ull*)(W21t + (e + 0) * D + d2);
                ull wa1 = *(const ull*)(W21t + (e + 1) * D + d2);
                ull wa2 = *(const ull*)(W21t + (e + 2) * D + d2);
                ull wa3 = *(const ull*)(W21t + (e + 3) * D + d2);
                ull wb0 = *(const ull*)(W22t + (e + 0) * D + d2);
                ull wb1 = *(const ull*)(W22t + (e + 1) * D + d2);
                ull wb2 = *(const ull*)(W22t + (e + 2) * D + d2);
                ull wb3 = *(const ull*)(W22t + (e + 3) * D + d2);
#pragma unroll
                for (int j = 0; j < 8; ++j) {
                    float4 xv = *(const float4*)&shX[j * XS + e];
                    float4 yv = *(const float4*)&shY[j * XS + e];
                    fma2(acc[j], pack2(xv.x, xv.x), wa0);
                    fma2(acc[j], pack2(xv.y, xv.y), wa1);
                    fma2(acc[j], pack2(xv.z, xv.z), wa2);
                    fma2(acc[j], pack2(xv.w, xv.w), wa3);
                    fma2(acc[j], pack2(yv.x, yv.x), wb0);
                    fma2(acc[j], pack2(yv.y, yv.y), wb1);
                    fma2(acc[j], pack2(yv.z, yv.z), wb2);
                    fma2(acc[j], pack2(yv.w, yv.w), wb3);
                }
            }
#pragma unroll
            for (int j = 0; j < 8; ++j)
                *(float2*)&shP[c4][j][d2] = unpack2(acc[j]);
        }
        __syncthreads();

        // reduce + leaky + pairwise shfl
        {
            float rx = 0.f, ry = 0.f, rz = 0.f, rw = 0.f;
#pragma unroll
            for (int c = 0; c < 4; ++c) {
                float4 p = *(float4*)&shP[c][g16][d4];
                rx += p.x; ry += p.y; rz += p.z; rw += p.w;
            }
            rx = leaky(rx); ry = leaky(ry); rz = leaky(rz); rw = leaky(rw);
            rx += __shfl_down_sync(0xffffffffu, rx, 16);
            ry += __shfl_down_sync(0xffffffffu, ry, 16);
            rz += __shfl_down_sync(0xffffffffu, rz, 16);
            rw += __shfl_down_sync(0xffffffffu, rw, 16);
            if ((t & 16) == 0)
                *(float4*)&shL[t >> 5][d4] = make_float4(rx, ry, rz, rw);
        }
        __syncthreads();

        // hop2 inputs
        if (t < 16) {
            int dd = t * 4;
            float Ax = 0.f, Ay = 0.f, Az = 0.f, Aw = 0.f;
#pragma unroll
            for (int wi = 0; wi < 4; ++wi) {
                float4 l = *(float4*)&shL[wi][dd];
                Ax += l.x; Ay += l.y; Az += l.z; Aw += l.w;
            }
            float w1 = avgw(c1);
            Ax *= w1; Ay *= w1; Az *= w1; Aw *= w1;
            *(float4*)&shX[dd] = make_float4(Ax + td4.x, Ay + td4.y, Az + td4.z, Aw + td4.w);
            *(float4*)&shY[dd] = make_float4(Ax * td4.x, Ay * td4.y, Az * td4.z, Aw * td4.w);
        }
        __syncthreads();

        // hop2 dual matvec W11/W12 (1 row)
        {
            const float* W11t = g_Wt + 2 * D * D;
            const float* W12t = g_Wt + 3 * D * D;
            ull acc = 0ull;
#pragma unroll
            for (int ep = 0; ep < 4; ++ep) {
                int e = c4 * 16 + ep * 4;
                float4 xv = *(const float4*)&shX[e];
                float4 yv = *(const float4*)&shY[e];
                fma2(acc, pack2(xv.x, xv.x), *(const ull*)(W11t + (e + 0) * D + d2));
                fma2(acc, pack2(xv.y, xv.y), *(const ull*)(W11t + (e + 1) * D + d2));
                fma2(acc, pack2(xv.z, xv.z), *(const ull*)(W11t + (e + 2) * D + d2));
                fma2(acc, pack2(xv.w, xv.w), *(const ull*)(W11t + (e + 3) * D + d2));
                fma2(acc, pack2(yv.x, yv.x), *(const ull*)(W12t + (e + 0) * D + d2));
                fma2(acc, pack2(yv.y, yv.y), *(const ull*)(W12t + (e + 1) * D + d2));
                fma2(acc, pack2(yv.z, yv.z), *(const ull*)(W12t + (e + 2) * D + d2));
                fma2(acc, pack2(yv.w, yv.w), *(const ull*)(W12t + (e + 3) * D + d2));
            }
            *(float2*)&shP[c4][0][d2] = unpack2(acc);
        }
        __syncthreads();

        if (t < 16) {
            int dd = t * 4;
            float rx = 0.f, ry = 0.f, rz = 0.f, rw = 0.f;
#pragma unroll
            for (int c = 0; c < 4; ++c) {
                float4 p = *(float4*)&shP[c][0][dd];
                rx += p.x; ry += p.y; rz += p.z; rw += p.w;
            }
            *(float4*)&g_dise[b * D + dd] =
                make_float4(leaky(rx), leaky(ry), leaky(rz), leaky(rw));
            __threadfence();
        }
        __syncthreads();
    }

    // ======================= completion + finalization =======================
    if (t == 0) {
        int old = atomicAdd(&g_cnt[b], 1);
        if (old == 8) { __threadfence(); sFin = 1; } else sFin = 0;
    }
    __syncthreads();
    if (!sFin) return;

    // --- finalization: es1 matvec + i-avg + W1u matvec + dot with dise ---
    float4 dz = make_float4(0.f, 0.f, 0.f, 0.f);
    int c1u = 0;
    if (t < 16) {
        dz = *(const float4*)&g_dise[b * D + t * 4];
        int4 m0 = __ldg((const int4*)(usu_1 + b * 8));
        int4 m1 = __ldg((const int4*)(usu_1 + b * 8 + 4));
        c1u = (m0.x != 0) + (m0.y != 0) + (m0.z != 0) + (m0.w != 0)
            + (m1.x != 0) + (m1.y != 0) + (m1.z != 0) + (m1.w != 0);
    }
    *(float4*)&shX[g16 * XS + d4] = *(const float4*)&g_UA[(b * 8 + g16) * D + d4];
    *(float4*)&shY[g16 * XS + d4] = *(const float4*)&g_UB[(b * 8 + g16) * D + d4];
    __syncthreads();

    // es1 dual matvec W21u/W22u
    {
        const float* W21t = g_Wt + 5 * D * D;
        const float* W22t = g_Wt + 6 * D * D;
        ull acc[8];
#pragma unroll
        for (int j = 0; j < 8; ++j) acc[j] = 0ull;
#pragma unroll
        for (int ep = 0; ep < 4; ++ep) {
            int e = c4 * 16 + ep * 4;
            ull wa0 = *(const ull*)(W21t + (e + 0) * D + d2);
            ull wa1 = *(const ull*)(W21t + (e + 1) * D + d2);
            ull wa2 = *(const ull*)(W21t + (e + 2) * D + d2);
            ull wa3 = *(const ull*)(W21t + (e + 3) * D + d2);
            ull wb0 = *(const ull*)(W22t + (e + 0) * D + d2);
            ull wb1 = *(const ull*)(W22t + (e + 1) * D + d2);
            ull wb2 = *(const ull*)(W22t + (e + 2) * D + d2);
            ull wb3 = *(const ull*)(W22t + (e + 3) * D + d2);
#pragma unroll
            for (int j = 0; j < 8; ++j) {
                float4 xv = *(const float4*)&shX[j * XS + e];
                float4 yv = *(const float4*)&shY[j * XS + e];
                fma2(acc[j], pack2(xv.x, xv.x), wa0);
                fma2(acc[j], pack2(xv.y, xv.y), wa1);
                fma2(acc[j], pack2(xv.z, xv.z), wa2);
                fma2(acc[j], pack2(xv.w, xv.w), wa3);
                fma2(acc[j], pack2(yv.x, yv.x), wb0);
                fma2(acc[j], pack2(yv.y, yv.y), wb1);
                fma2(acc[j], pack2(yv.z, yv.z), wb2);
                fma2(acc[j], pack2(yv.w, yv.w), wb3);
            }
        }
#pragma unroll
        for (int j = 0; j < 8; ++j)
            *(float2*)&shP[c4][j][d2] = unpack2(acc[j]);
    }
    __syncthreads();

    // reduce + leaky + pairwise shfl
    {
        float rx = 0.f, ry = 0.f, rz = 0.f, rw = 0.f;
#pragma unroll
        for (int c = 0; c < 4; ++c) {
            float4 p = *(float4*)&shP[c][g16][d4];
            rx += p.x; ry += p.y; rz += p.z; rw += p.w;
        }
        rx = leaky(rx); ry = leaky(ry); rz = leaky(rz); rw = leaky(rw);
        rx += __shfl_down_sync(0xffffffffu, rx, 16);
        ry += __shfl_down_sync(0xffffffffu, ry, 16);
        rz += __shfl_down_sync(0xffffffffu, rz, 16);
        rw += __shfl_down_sync(0xffffffffu, rw, 16);
        if ((t & 16) == 0)
            *(float4*)&shL[t >> 5][d4] = make_float4(rx, ry, rz, rw);
    }
    __syncthreads();

    // i-avg
    if (t < 16) {
        int dd = t * 4;
        float Tx = 0.f, Ty = 0.f, Tz = 0.f, Tw = 0.f;
#pragma unroll
        for (int wi = 0; wi < 4; ++wi) {
            float4 l = *(float4*)&shL[wi][dd];
            Tx += l.x; Ty += l.y; Tz += l.z; Tw += l.w;
        }
        float w1 = avgw(c1u);
        *(float4*)&shX[dd] = make_float4(Tx * w1, Ty * w1, Tz * w1, Tw * w1);
    }
    __syncthreads();

    // emb_user matvec W1u (1 row)
    {
        const float* W1t = g_Wt + 7 * D * D;
        ull acc = 0ull;
#pragma unroll
        for (int ep = 0; ep < 4; ++ep) {
            int e = c4 * 16 + ep * 4;
            float4 xv = *(const float4*)&shX[e];
            fma2(acc, pack2(xv.x, xv.x), *(const ull*)(W1t + (e + 0) * D + d2));
            fma2(acc, pack2(xv.y, xv.y), *(const ull*)(W1t + (e + 1) * D + d2));
            fma2(acc, pack2(xv.z, xv.z), *(const ull*)(W1t + (e + 2) * D + d2));
            fma2(acc, pack2(xv.w, xv.w), *(const ull*)(W1t + (e + 3) * D + d2));
        }
        *(float2*)&shP[c4][0][d2] = unpack2(acc);
    }
    __syncthreads();

    // final reduce + dot with emb_dise
    if (t < 16) {
        int dd = t * 4;
        float rx = 0.f, ry = 0.f, rz = 0.f, rw = 0.f;
#pragma unroll
        for (int c = 0; c < 4; ++c) {
            float4 p = *(float4*)&shP[c][0][dd];
            rx += p.x; ry += p.y; rz += p.z; rw += p.w;
        }
        float v = leaky(rx) * dz.x + leaky(ry) * dz.y +
                  leaky(rz) * dz.z + leaky(rw) * dz.w;
        v += __shfl_down_sync(0x0000ffffu, v, 8, 16);
        v += __shfl_down_sync(0x0000ffffu, v, 4, 16);
        v += __shfl_down_sync(0x0000ffffu, v, 2, 16);
        v += __shfl_down_sync(0x0000ffffu, v, 1, 16);
        if (t == 0) out[b] = v;
    }
}

// ---------------------------------------------------------------------------
extern "C" void kernel_launch(void* const* d_in, const int* in_sizes, int n_in,
                              void* d_out, int out_size) {
    const float* E_s = (const float*)d_in[0];
    const float* E_d = (const float*)d_in[1];
    // weights: W_dsd_21, W_dsd_22, W_dsd_11, W_dsd_12, W_usu_3, W_usu_21, W_usu_22, W_usu_1
    k_prep<<<66, 512>>>((const float*)d_in[2], (const float*)d_in[3],
                        (const float*)d_in[4], (const float*)d_in[5],
                        (const float*)d_in[6], (const float*)d_in[7],
                        (const float*)d_in[8], (const float*)d_in[9]);

    k_inner<<<NB * 9, 128>>>(E_s, E_d,
                             (const int*)d_in[10], (const int*)d_in[11],
                             (const int*)d_in[12], (const int*)d_in[13],
                             (const int*)d_in[14], (const int*)d_in[15],
                             (float*)d_out);
}

// round 11
// speedup vs baseline: 1.2131x; 1.0621x over previous
#include <cuda_runtime.h>
#include <cuda_fp16.h>

#define D 64
#define NB 1024
#define XS 68   // float smem row stride (272B, 16B-aligned)

#define NS_ROWS 50001   // E_s rows
#define ND_ROWS 2001    // E_d rows

// Scratch (allocation-free rule: __device__ globals)
__device__ __align__(16) float g_Wt[8 * D * D];      // Wt[m][e*64+d] = W[m][d*64+e]
__device__ __align__(16) __half g_Es2[NS_ROWS * D];  // fp16 E_s (6.4MB)
__device__ __align__(16) __half g_Ed2[ND_ROWS * D];  // fp16 E_d
__device__ __align__(16) float g_UA[NB * 8 * D];     // u1 + S
__device__ __align__(16) float g_UB[NB * 8 * D];     // S * u1
__device__ __align__(16) float g_dise[NB * D];       // emb_dise
__device__ int g_cnt[NB];                            // completion counters

typedef unsigned long long ull;

__device__ __forceinline__ float leaky(float x) { return fmaxf(x, 0.2f * x); }
__device__ __forceinline__ float avgw(int cnt)  { return cnt > 0 ? 1.0f / ((float)cnt + 1e-8f) : 0.0f; }

__device__ __forceinline__ ull pack2(float x, float y) {
    ull r; asm("mov.b64 %0, {%1, %2};" : "=l"(r) : "f"(x), "f"(y)); return r;
}
__device__ __forceinline__ float2 unpack2(ull v) {
    float2 f; asm("mov.b64 {%0, %1}, %2;" : "=f"(f.x), "=f"(f.y) : "l"(v)); return f;
}
__device__ __forceinline__ void fma2(ull& acc, ull a, ull b) {
    asm("fma.rn.f32x2 %0, %1, %2, %3;" : "=l"(acc) : "l"(a), "l"(b), "l"(acc));
}

// load 4 halves (8B = one wavefront-slice) and widen to float4
__device__ __forceinline__ float4 ldh4(const __half* p) {
    uint2 raw = *(const uint2*)p;
    __half2 h0 = *reinterpret_cast<__half2*>(&raw.x);
    __half2 h1 = *reinterpret_cast<__half2*>(&raw.y);
    float2 a = __half22float2(h0), b = __half22float2(h1);
    return make_float4(a.x, a.y, b.x, b.y);
}

// ---------------------------------------------------------------------------
// K0: prep — fp16 conversion of E_s/E_d, weight transpose, counter zeroing
// grid layout: [0,CV_S): Es, [CV_S,CV_S+CV_D): Ed, then 64 transpose, 4 cnt
// ---------------------------------------------------------------------------
#define CV_S ((NS_ROWS * D / 4 + 255) / 256)   // 3126
#define CV_D ((ND_ROWS * D / 4 + 255) / 256)   // 126
#define TP_B 64
#define CN_B 4
#define PREP_GRID (CV_S + CV_D + TP_B + CN_B)

__global__ void __launch_bounds__(256)
k_prep(const float* __restrict__ E_s, const float* __restrict__ E_d,
       const float* __restrict__ w0, const float* __restrict__ w1,
       const float* __restrict__ w2, const float* __restrict__ w3,
       const float* __restrict__ w4, const float* __restrict__ w5,
       const float* __restrict__ w6, const float* __restrict__ w7) {
    int bid = blockIdx.x, t = threadIdx.x;
    if (bid < CV_S) {
        int i = bid * 256 + t;
        if (i < NS_ROWS * D / 4) {
            float4 v = *(const float4*)(E_s + i * 4);
            __half2 h0 = __floats2half2_rn(v.x, v.y);
            __half2 h1 = __floats2half2_rn(v.z, v.w);
            uint2 u;
            u.x = *reinterpret_cast<unsigned*>(&h0);
            u.y = *reinterpret_cast<unsigned*>(&h1);
            *(uint2*)(g_Es2 + i * 4) = u;
        }
    } else if (bid < CV_S + CV_D) {
        int i = (bid - CV_S) * 256 + t;
        if (i < ND_ROWS * D / 4) {
            float4 v = *(const float4*)(E_d + i * 4);
            __half2 h0 = __floats2half2_rn(v.x, v.y);
            __half2 h1 = __floats2half2_rn(v.z, v.w);
            uint2 u;
            u.x = *reinterpret_cast<unsigned*>(&h0);
            u.y = *reinterpret_cast<unsigned*>(&h1);
            *(uint2*)(g_Ed2 + i * 4) = u;
        }
    } else if (bid < CV_S + CV_D + TP_B) {
        const float* Ws[8] = {w0, w1, w2, w3, w4, w5, w6, w7};
        int k = (bid - CV_S - CV_D) * 256 + t;   // [0, 16384)
#pragma unroll
        for (int p = 0; p < 2; ++p) {
            int idx = k + p * 16384;             // linear: m,d,e
            int m = idx >> 12, de = idx & 4095;
            int d = de >> 6, e = de & 63;
            g_Wt[m * D * D + e * D + d] = Ws[m][d * D + e];
        }
    } else {
        int i = (bid - CV_S - CV_D - TP_B) * 256 + t;
        g_cnt[i] = 0;
    }
}

// ---------------------------------------------------------------------------
// K1: blocks [0, NB): dsd per b.  blocks [NB, 9*NB): usu inner per (b,g).
// 128 threads. Gather: fp16 rows (1 wavefront/row). Matvec: 4 warp-chunks x
// 32 lanes (2 dims), float4-LDS + register dup. 9th finisher finalizes.
// ---------------------------------------------------------------------------
__global__ void __launch_bounds__(128, 7)
k_inner(const int* __restrict__ label,
        const int* __restrict__ dsd_1, const int* __restrict__ dsd_2,
        const int* __restrict__ usu_1, const int* __restrict__ usu_2,
        const int* __restrict__ usu_3, float* __restrict__ out) {
    int t = threadIdx.x;
    int g16 = t >> 4, lane = t & 15, d4 = lane * 4;
    int c4 = t >> 5, d2 = (t & 31) * 2;

    __shared__ __align__(16) float shX[8 * XS];
    __shared__ __align__(16) float shY[8 * XS];
    __shared__ float shP[4][8][D];
    __shared__ float shL[4][XS];
    __shared__ int sFin;

    int b;

    if (blockIdx.x >= NB) {
        // ===================== usu inner: one (b,g) per block ================
        int bg = blockIdx.x - NB;
        b = bg >> 3;

        float4 u = make_float4(0.f, 0.f, 0.f, 0.f);
        int c2 = 0;
        if (t < 16) {
            int iu = __ldg(usu_1 + bg);
            u = ldh4(g_Es2 + iu * D + t * 4);
            int4 m0 = __ldg((const int4*)(usu_2 + bg * 8));
            int4 m1 = __ldg((const int4*)(usu_2 + bg * 8 + 4));
            c2 = (m0.x != 0) + (m0.y != 0) + (m0.z != 0) + (m0.w != 0)
               + (m1.x != 0) + (m1.y != 0) + (m1.z != 0) + (m1.w != 0);
        }

        const int4* ip = (const int4*)(usu_3 + (bg * 8 + g16) * 16);
        int4 i0 = __ldg(ip), i1 = __ldg(ip + 1), i2 = __ldg(ip + 2), i3 = __ldg(ip + 3);
        int cnt = (i0.x != 0) + (i0.y != 0) + (i0.z != 0) + (i0.w != 0)
                + (i1.x != 0) + (i1.y != 0) + (i1.z != 0) + (i1.w != 0)
                + (i2.x != 0) + (i2.y != 0) + (i2.z != 0) + (i2.w != 0)
                + (i3.x != 0) + (i3.y != 0) + (i3.z != 0) + (i3.w != 0);

        float sx = 0.f, sy = 0.f, sz = 0.f, sw = 0.f;
#define ACC(ix) { float4 v = ldh4(g_Es2 + (ix) * D + d4); \
                  sx += v.x; sy += v.y; sz += v.z; sw += v.w; }
        ACC(i0.x) ACC(i0.y) ACC(i0.z) ACC(i0.w)
        ACC(i1.x) ACC(i1.y) ACC(i1.z) ACC(i1.w)
        ACC(i2.x) ACC(i2.y) ACC(i2.z) ACC(i2.w)
        ACC(i3.x) ACC(i3.y) ACC(i3.z) ACC(i3.w)
#undef ACC
        float w = avgw(cnt);
        *(float4*)&shX[g16 * XS + d4] = make_float4(sx * w, sy * w, sz * w, sw * w);
        __syncthreads();

        // matvec W3: warp-chunk c4 (16 e = 4 quads), dims d2..d2+1, 8 rows
        {
            const float* W3t = g_Wt + 4 * D * D;
            ull acc[8];
#pragma unroll
            for (int j = 0; j < 8; ++j) acc[j] = 0ull;
#pragma unroll
            for (int ep = 0; ep < 4; ++ep) {
                int e = c4 * 16 + ep * 4;
                ull w0 = *(const ull*)(W3t + (e + 0) * D + d2);
                ull w1 = *(const ull*)(W3t + (e + 1) * D + d2);
                ull w2 = *(const ull*)(W3t + (e + 2) * D + d2);
                ull w3 = *(const ull*)(W3t + (e + 3) * D + d2);
#pragma unroll
                for (int j = 0; j < 8; ++j) {
                    float4 xv = *(const float4*)&shX[j * XS + e];
                    fma2(acc[j], pack2(xv.x, xv.x), w0);
                    fma2(acc[j], pack2(xv.y, xv.y), w1);
                    fma2(acc[j], pack2(xv.z, xv.z), w2);
                    fma2(acc[j], pack2(xv.w, xv.w), w3);
                }
            }
#pragma unroll
            for (int j = 0; j < 8; ++j)
                *(float2*)&shP[c4][j][d2] = unpack2(acc[j]);
        }
        __syncthreads();

        // reduce 4 chunks + leaky + pairwise j via shfl
        {
            float rx = 0.f, ry = 0.f, rz = 0.f, rw = 0.f;
#pragma unroll
            for (int c = 0; c < 4; ++c) {
                float4 p = *(float4*)&shP[c][g16][d4];
                rx += p.x; ry += p.y; rz += p.z; rw += p.w;
            }
            rx = leaky(rx); ry = leaky(ry); rz = leaky(rz); rw = leaky(rw);
            rx += __shfl_down_sync(0xffffffffu, rx, 16);
            ry += __shfl_down_sync(0xffffffffu, ry, 16);
            rz += __shfl_down_sync(0xffffffffu, rz, 16);
            rw += __shfl_down_sync(0xffffffffu, rw, 16);
            if ((t & 16) == 0)
                *(float4*)&shL[t >> 5][d4] = make_float4(rx, ry, rz, rw);
        }
        __syncthreads();

        if (t < 16) {
            int dd = t * 4;
            float Sx = 0.f, Sy = 0.f, Sz = 0.f, Sw = 0.f;
#pragma unroll
            for (int wi = 0; wi < 4; ++wi) {
                float4 l = *(float4*)&shL[wi][dd];
                Sx += l.x; Sy += l.y; Sz += l.z; Sw += l.w;
            }
            float w2 = avgw(c2);
            Sx *= w2; Sy *= w2; Sz *= w2; Sw *= w2;
            *(float4*)&g_UA[bg * D + dd] = make_float4(u.x + Sx, u.y + Sy, u.z + Sz, u.w + Sw);
            *(float4*)&g_UB[bg * D + dd] = make_float4(Sx * u.x, Sy * u.y, Sz * u.z, Sw * u.w);
            __threadfence();
        }
        __syncthreads();
    } else {
        // ===================== dsd full path: one b per block ================
        b = blockIdx.x;

        float4 td4 = make_float4(0.f, 0.f, 0.f, 0.f);
        int c1 = 0;
        if (t < 16) {
            int lb = __ldg(label + b);
            td4 = ldh4(g_Ed2 + lb * D + t * 4);
            int4 m0 = __ldg((const int4*)(dsd_1 + b * 8));
            int4 m1 = __ldg((const int4*)(dsd_1 + b * 8 + 4));
            c1 = (m0.x != 0) + (m0.y != 0) + (m0.z != 0) + (m0.w != 0)
               + (m1.x != 0) + (m1.y != 0) + (m1.z != 0) + (m1.w != 0);
        }

        int ies = __ldg(dsd_1 + b * 8 + g16);
        const int4* ip = (const int4*)(dsd_2 + (b * 8 + g16) * 8);
        int4 i0 = __ldg(ip), i1 = __ldg(ip + 1);
        int cnt = (i0.x != 0) + (i0.y != 0) + (i0.z != 0) + (i0.w != 0)
                + (i1.x != 0) + (i1.y != 0) + (i1.z != 0) + (i1.w != 0);

        float4 es = ldh4(g_Es2 + ies * D + d4);
        float sx = 0.f, sy = 0.f, sz = 0.f, sw = 0.f;
#define ACC(ix) { float4 v = ldh4(g_Ed2 + (ix) * D + d4); \
                  sx += v.x; sy += v.y; sz += v.z; sw += v.w; }
        ACC(i0.x) ACC(i0.y) ACC(i0.z) ACC(i0.w)
        ACC(i1.x) ACC(i1.y) ACC(i1.z) ACC(i1.w)
#undef ACC
        float w = avgw(cnt);
        float ax = sx * w, ay = sy * w, az = sz * w, aw = sw * w;
        *(float4*)&shX[g16 * XS + d4] = make_float4(es.x + ax, es.y + ay, es.z + az, es.w + aw);
        *(float4*)&shY[g16 * XS + d4] = make_float4(ax * es.x, ay * es.y, az * es.z, aw * es.w);
        __syncthreads();

        // hop1 dual matvec W21/W22
        {
            const float* W21t = g_Wt + 0 * D * D;
            const float* W22t = g_Wt + 1 * D * D;
            ull acc[8];
#pragma unroll
            for (int j = 0; j < 8; ++j) acc[j] = 0ull;
#pragma unroll
            for (int ep = 0; ep < 4; ++ep) {
                int e = c4 * 16 + ep * 4;
                ull wa0 = *(const ull*)(W21t + (e + 0) * D + d2);
                ull wa1 = *(const ull*)(W21t + (e + 1) * D + d2);
                ull wa2 = *(const ull*)(W21t + (e + 2) * D + d2);
                ull wa3 = *(const ull*)(W21t + (e + 3) * D + d2);
                ull wb0 = *(const ull*)(W22t + (e + 0) * D + d2);
                ull wb1 = *(const ull*)(W22t + (e + 1) * D + d2);
                ull wb2 = *(const ull*)(W22t + (e + 2) * D + d2);
                ull wb3 = *(const ull*)(W22t + (e + 3) * D + d2);
#pragma unroll
                for (int j = 0; j < 8; ++j) {
                    float4 xv = *(const float4*)&shX[j * XS + e];
                    float4 yv = *(const float4*)&shY[j * XS + e];
                    fma2(acc[j], pack2(xv.x, xv.x), wa0);
                    fma2(acc[j], pack2(xv.y, xv.y), wa1);
                    fma2(acc[j], pack2(xv.z, xv.z), wa2);
                    fma2(acc[j], pack2(xv.w, xv.w), wa3);
                    fma2(acc[j], pack2(yv.x, yv.x), wb0);
                    fma2(acc[j], pack2(yv.y, yv.y), wb1);
                    fma2(acc[j], pack2(yv.z, yv.z), wb2);
                    fma2(acc[j], pack2(yv.w, yv.w), wb3);
                }
            }
#pragma unroll
            for (int j = 0; j < 8; ++j)
                *(float2*)&shP[c4][j][d2] = unpack2(acc[j]);
        }
        __syncthreads();

        // reduce + leaky + pairwise shfl
        {
            float rx = 0.f, ry = 0.f, rz = 0.f, rw = 0.f;
#pragma unroll
            for (int c = 0; c < 4; ++c) {
                float4 p = *(float4*)&shP[c][g16][d4];
                rx += p.x; ry += p.y; rz += p.z; rw += p.w;
            }
            rx = leaky(rx); ry = leaky(ry); rz = leaky(rz); rw = leaky(rw);
            rx += __shfl_down_sync(0xffffffffu, rx, 16);
            ry += __shfl_down_sync(0xffffffffu, ry, 16);
            rz += __shfl_down_sync(0xffffffffu, rz, 16);
            rw += __shfl_down_sync(0xffffffffu, rw, 16);
            if ((t & 16) == 0)
                *(float4*)&shL[t >> 5][d4] = make_float4(rx, ry, rz, rw);
        }
        __syncthreads();

        // hop2 inputs
        if (t < 16) {
            int dd = t * 4;
            float Ax = 0.f, Ay = 0.f, Az = 0.f, Aw = 0.f;
#pragma unroll
            for (int wi = 0; wi < 4; ++wi) {
                float4 l = *(float4*)&shL[wi][dd];
                Ax += l.x; Ay += l.y; Az += l.z; Aw += l.w;
            }
            float w1 = avgw(c1);
            Ax *= w1; Ay *= w1; Az *= w1; Aw *= w1;
            *(float4*)&shX[dd] = make_float4(Ax + td4.x, Ay + td4.y, Az + td4.z, Aw + td4.w);
            *(float4*)&shY[dd] = make_float4(Ax * td4.x, Ay * td4.y, Az * td4.z, Aw * td4.w);
        }
        __syncthreads();

        // hop2 dual matvec W11/W12 (1 row)
        {
            const float* W11t = g_Wt + 2 * D * D;
            const float* W12t = g_Wt + 3 * D * D;
            ull acc = 0ull;
#pragma unroll
            for (int ep = 0; ep < 4; ++ep) {
                int e = c4 * 16 + ep * 4;
                float4 xv = *(const float4*)&shX[e];
                float4 yv = *(const float4*)&shY[e];
                fma2(acc, pack2(xv.x, xv.x), *(const ull*)(W11t + (e + 0) * D + d2));
                fma2(acc, pack2(xv.y, xv.y), *(const ull*)(W11t + (e + 1) * D + d2));
                fma2(acc, pack2(xv.z, xv.z), *(const ull*)(W11t + (e + 2) * D + d2));
                fma2(acc, pack2(xv.w, xv.w), *(const ull*)(W11t + (e + 3) * D + d2));
                fma2(acc, pack2(yv.x, yv.x), *(const ull*)(W12t + (e + 0) * D + d2));
                fma2(acc, pack2(yv.y, yv.y), *(const ull*)(W12t + (e + 1) * D + d2));
                fma2(acc, pack2(yv.z, yv.z), *(const ull*)(W12t + (e + 2) * D + d2));
                fma2(acc, pack2(yv.w, yv.w), *(const ull*)(W12t + (e + 3) * D + d2));
            }
            *(float2*)&shP[c4][0][d2] = unpack2(acc);
        }
        __syncthreads();

        if (t < 16) {
            int dd = t * 4;
            float rx = 0.f, ry = 0.f, rz = 0.f, rw = 0.f;
#pragma unroll
            for (int c = 0; c < 4; ++c) {
                float4 p = *(float4*)&shP[c][0][dd];
                rx += p.x; ry += p.y; rz += p.z; rw += p.w;
            }
            *(float4*)&g_dise[b * D + dd] =
                make_float4(leaky(rx), leaky(ry), leaky(rz), leaky(rw));
            __threadfence();
        }
        __syncthreads();
    }

    // ======================= completion + finalization =======================
    if (t == 0) {
        int old = atomicAdd(&g_cnt[b], 1);
        if (old == 8) { __threadfence(); sFin = 1; } else sFin = 0;
    }
    __syncthreads();
    if (!sFin) return;

    // --- finalization: es1 matvec + i-avg + W1u matvec + dot with dise ---
    float4 dz = make_float4(0.f, 0.f, 0.f, 0.f);
    int c1u = 0;
    if (t < 16) {
        dz = *(const float4*)&g_dise[b * D + t * 4];
        int4 m0 = __ldg((const int4*)(usu_1 + b * 8));
        int4 m1 = __ldg((const int4*)(usu_1 + b * 8 + 4));
        c1u = (m0.x != 0) + (m0.y != 0) + (m0.z != 0) + (m0.w != 0)
            + (m1.x != 0) + (m1.y != 0) + (m1.z != 0) + (m1.w != 0);
    }
    *(float4*)&shX[g16 * XS + d4] = *(const float4*)&g_UA[(b * 8 + g16) * D + d4];
    *(float4*)&shY[g16 * XS + d4] = *(const float4*)&g_UB[(b * 8 + g16) * D + d4];
    __syncthreads();

    // es1 dual matvec W21u/W22u
    {
        const float* W21t = g_Wt + 5 * D * D;
        const float* W22t = g_Wt + 6 * D * D;
        ull acc[8];
#pragma unroll
        for (int j = 0; j < 8; ++j) acc[j] = 0ull;
#pragma unroll
        for (int ep = 0; ep < 4; ++ep) {
            int e = c4 * 16 + ep * 4;
            ull wa0 = *(const ull*)(W21t + (e + 0) * D + d2);
            ull wa1 = *(const ull*)(W21t + (e + 1) * D + d2);
            ull wa2 = *(const ull*)(W21t + (e + 2) * D + d2);
            ull wa3 = *(const ull*)(W21t + (e + 3) * D + d2);
            ull wb0 = *(const ull*)(W22t + (e + 0) * D + d2);
            ull wb1 = *(const ull*)(W22t + (e + 1) * D + d2);
            ull wb2 = *(const ull*)(W22t + (e + 2) * D + d2);
            ull wb3 = *(const ull*)(W22t + (e + 3) * D + d2);
#pragma unroll
            for (int j = 0; j < 8; ++j) {
                float4 xv = *(const float4*)&shX[j * XS + e];
                float4 yv = *(const float4*)&shY[j * XS + e];
                fma2(acc[j], pack2(xv.x, xv.x), wa0);
                fma2(acc[j], pack2(xv.y, xv.y), wa1);
                fma2(acc[j], pack2(xv.z, xv.z), wa2);
                fma2(acc[j], pack2(xv.w, xv.w), wa3);
                fma2(acc[j], pack2(yv.x, yv.x), wb0);
                fma2(acc[j], pack2(yv.y, yv.y), wb1);
                fma2(acc[j], pack2(yv.z, yv.z), wb2);
                fma2(acc[j], pack2(yv.w, yv.w), wb3);
            }
        }
#pragma unroll
        for (int j = 0; j < 8; ++j)
            *(float2*)&shP[c4][j][d2] = unpack2(acc[j]);
    }
    __syncthreads();

    // reduce + leaky + pairwise shfl
    {
        float rx = 0.f, ry = 0.f, rz = 0.f, rw = 0.f;
#pragma unroll
        for (int c = 0; c < 4; ++c) {
            float4 p = *(float4*)&shP[c][g16][d4];
            rx += p.x; ry += p.y; rz += p.z; rw += p.w;
        }
        rx = leaky(rx); ry = leaky(ry); rz = leaky(rz); rw = leaky(rw);
        rx += __shfl_down_sync(0xffffffffu, rx, 16);
        ry += __shfl_down_sync(0xffffffffu, ry, 16);
        rz += __shfl_down_sync(0xffffffffu, rz, 16);
        rw += __shfl_down_sync(0xffffffffu, rw, 16);
        if ((t & 16) == 0)
            *(float4*)&shL[t >> 5][d4] = make_float4(rx, ry, rz, rw);
    }
    __syncthreads();

    // i-avg
    if (t < 16) {
        int dd = t * 4;
        float Tx = 0.f, Ty = 0.f, Tz = 0.f, Tw = 0.f;
#pragma unroll
        for (int wi = 0; wi < 4; ++wi) {
            float4 l = *(float4*)&shL[wi][dd];
            Tx += l.x; Ty += l.y; Tz += l.z; Tw += l.w;
        }
        float w1 = avgw(c1u);
        *(float4*)&shX[dd] = make_float4(Tx * w1, Ty * w1, Tz * w1, Tw * w1);
    }
    __syncthreads();

    // emb_user matvec W1u (1 row)
    {
        const float* W1t = g_Wt + 7 * D * D;
        ull acc = 0ull;
#pragma unroll
        for (int ep = 0; ep < 4; ++ep) {
            int e = c4 * 16 + ep * 4;
            float4 xv = *(const float4*)&shX[e];
            fma2(acc, pack2(xv.x, xv.x), *(const ull*)(W1t + (e + 0) * D + d2));
            fma2(acc, pack2(xv.y, xv.y), *(const ull*)(W1t + (e + 1) * D + d2));
            fma2(acc, pack2(xv.z, xv.z), *(const ull*)(W1t + (e + 2) * D + d2));
            fma2(acc, pack2(xv.w, xv.w), *(const ull*)(W1t + (e + 3) * D + d2));
        }
        *(float2*)&shP[c4][0][d2] = unpack2(acc);
    }
    __syncthreads();

    // final reduce + dot with emb_dise
    if (t < 16) {
        int dd = t * 4;
        float rx = 0.f, ry = 0.f, rz = 0.f, rw = 0.f;
#pragma unroll
        for (int c = 0; c < 4; ++c) {
            float4 p = *(float4*)&shP[c][0][dd];
            rx += p.x; ry += p.y; rz += p.z; rw += p.w;
        }
        float v = leaky(rx) * dz.x + leaky(ry) * dz.y +
                  leaky(rz) * dz.z + leaky(rw) * dz.w;
        v += __shfl_down_sync(0x0000ffffu, v, 8, 16);
        v += __shfl_down_sync(0x0000ffffu, v, 4, 16);
        v += __shfl_down_sync(0x0000ffffu, v, 2, 16);
        v += __shfl_down_sync(0x0000ffffu, v, 1, 16);
        if (t == 0) out[b] = v;
    }
}

// ---------------------------------------------------------------------------
extern "C" void kernel_launch(void* const* d_in, const int* in_sizes, int n_in,
                              void* d_out, int out_size) {
    const float* E_s = (const float*)d_in[0];
    const float* E_d = (const float*)d_in[1];
    // weights: W_dsd_21, W_dsd_22, W_dsd_11, W_dsd_12, W_usu_3, W_usu_21, W_usu_22, W_usu_1
    k_prep<<<PREP_GRID, 256>>>(E_s, E_d,
                               (const float*)d_in[2], (const float*)d_in[3],
                               (const float*)d_in[4], (const float*)d_in[5],
                               (const float*)d_in[6], (const float*)d_in[7],
                               (const float*)d_in[8], (const float*)d_in[9]);

    k_inner<<<NB * 9, 128>>>((const int*)d_in[10], (const int*)d_in[11],
                             (const int*)d_in[12], (const int*)d_in[13],
                             (const int*)d_in[14], (const int*)d_in[15],
                             (float*)d_out);
}

// round 12
// speedup vs baseline: 1.2854x; 1.0596x over previous
#include <cuda_runtime.h>
#include <cuda_fp16.h>

#define D 64
#define NB 1024
#define XS 68   // float smem row stride (272B, 16B-aligned)

#define NS_ROWS 50001   // E_s rows
#define ND_ROWS 2001    // E_d rows

// Scratch (allocation-free rule: __device__ globals)
__device__ __align__(16) __half g_Wt2[8 * D * D];    // fp16 Wt[m][e*64+d]
__device__ __align__(16) __half g_Es2[NS_ROWS * D];  // fp16 E_s (6.4MB)
__device__ __align__(16) __half g_Ed2[ND_ROWS * D];  // fp16 E_d
__device__ __align__(16) float g_UA[NB * 8 * D];     // u1 + S
__device__ __align__(16) float g_UB[NB * 8 * D];     // S * u1
__device__ __align__(16) float g_dise[NB * D];       // emb_dise
__device__ int g_cnt[NB];                            // completion counters

typedef unsigned long long ull;

__device__ __forceinline__ float leaky(float x) { return fmaxf(x, 0.2f * x); }
__device__ __forceinline__ float avgw(int cnt)  { return cnt > 0 ? 1.0f / ((float)cnt + 1e-8f) : 0.0f; }

__device__ __forceinline__ ull pack2(float x, float y) {
    ull r; asm("mov.b64 %0, {%1, %2};" : "=l"(r) : "f"(x), "f"(y)); return r;
}
__device__ __forceinline__ float2 unpack2(ull v) {
    float2 f; asm("mov.b64 {%0, %1}, %2;" : "=f"(f.x), "=f"(f.y) : "l"(v)); return f;
}
__device__ __forceinline__ void fma2(ull& acc, ull a, ull b) {
    asm("fma.rn.f32x2 %0, %1, %2, %3;" : "=l"(acc) : "l"(a), "l"(b), "l"(acc));
}

// load 4 halves (8B) and widen to float4
__device__ __forceinline__ float4 ldh4(const __half* p) {
    uint2 raw = *(const uint2*)p;
    __half2 h0 = *reinterpret_cast<__half2*>(&raw.x);
    __half2 h1 = *reinterpret_cast<__half2*>(&raw.y);
    float2 a = __half22float2(h0), b = __half22float2(h1);
    return make_float4(a.x, a.y, b.x, b.y);
}

// load 2 fp16 weights (4B = 1 wavefront/warp) and widen+pack to fma2 operand
__device__ __forceinline__ ull ldw2(const __half* p) {
    __half2 h = *(const __half2*)p;
    float2 f = __half22float2(h);
    return pack2(f.x, f.y);
}

// ---------------------------------------------------------------------------
// K0: prep — fp16 conversion of E_s/E_d, fp16 weight transpose, counters
// ---------------------------------------------------------------------------
#define CV_S ((NS_ROWS * D / 4 + 255) / 256)   // 3126
#define CV_D ((ND_ROWS * D / 4 + 255) / 256)   // 126
#define TP_B 64
#define CN_B 4
#define PREP_GRID (CV_S + CV_D + TP_B + CN_B)

__global__ void __launch_bounds__(256)
k_prep(const float* __restrict__ E_s, const float* __restrict__ E_d,
       const float* __restrict__ w0, const float* __restrict__ w1,
       const float* __restrict__ w2, const float* __restrict__ w3,
       const float* __restrict__ w4, const float* __restrict__ w5,
       const float* __restrict__ w6, const float* __restrict__ w7) {
    int bid = blockIdx.x, t = threadIdx.x;
    if (bid < CV_S) {
        int i = bid * 256 + t;
        if (i < NS_ROWS * D / 4) {
            float4 v = *(const float4*)(E_s + i * 4);
            __half2 h0 = __floats2half2_rn(v.x, v.y);
            __half2 h1 = __floats2half2_rn(v.z, v.w);
            uint2 u;
            u.x = *reinterpret_cast<unsigned*>(&h0);
            u.y = *reinterpret_cast<unsigned*>(&h1);
            *(uint2*)(g_Es2 + i * 4) = u;
        }
    } else if (bid < CV_S + CV_D) {
        int i = (bid - CV_S) * 256 + t;
        if (i < ND_ROWS * D / 4) {
            float4 v = *(const float4*)(E_d + i * 4);
            __half2 h0 = __floats2half2_rn(v.x, v.y);
            __half2 h1 = __floats2half2_rn(v.z, v.w);
            uint2 u;
            u.x = *reinterpret_cast<unsigned*>(&h0);
            u.y = *reinterpret_cast<unsigned*>(&h1);
            *(uint2*)(g_Ed2 + i * 4) = u;
        }
    } else if (bid < CV_S + CV_D + TP_B) {
        const float* Ws[8] = {w0, w1, w2, w3, w4, w5, w6, w7};
        int k = (bid - CV_S - CV_D) * 256 + t;   // [0, 16384)
#pragma unroll
        for (int p = 0; p < 2; ++p) {
            int idx = k + p * 16384;             // linear: m,d,e
            int m = idx >> 12, de = idx & 4095;
            int d = de >> 6, e = de & 63;
            g_Wt2[m * D * D + e * D + d] = __float2half_rn(Ws[m][d * D + e]);
        }
    } else {
        int i = (bid - CV_S - CV_D - TP_B) * 256 + t;
        g_cnt[i] = 0;
    }
}

// ---------------------------------------------------------------------------
// K1: blocks [0, NB): dsd per b.  blocks [NB, 9*NB): usu inner per (b,g).
// 128 threads. Gather: fp16 rows (1 wavefront/row). Matvec: 4 warp-chunks x
// 32 lanes (2 dims), float4-LDS + register dup, fp16 weights (1 wf/load).
// 9th finisher per b runs finalization in place.
// ---------------------------------------------------------------------------
__global__ void __launch_bounds__(128, 7)
k_inner(const int* __restrict__ label,
        const int* __restrict__ dsd_1, const int* __restrict__ dsd_2,
        const int* __restrict__ usu_1, const int* __restrict__ usu_2,
        const int* __restrict__ usu_3, float* __restrict__ out) {
    int t = threadIdx.x;
    int g16 = t >> 4, lane = t & 15, d4 = lane * 4;
    int c4 = t >> 5, d2 = (t & 31) * 2;

    __shared__ __align__(16) float shX[8 * XS];
    __shared__ __align__(16) float shY[8 * XS];
    __shared__ float shP[4][8][D];
    __shared__ float shL[4][XS];
    __shared__ int sFin;

    int b;

    if (blockIdx.x >= NB) {
        // ===================== usu inner: one (b,g) per block ================
        int bg = blockIdx.x - NB;
        b = bg >> 3;

        float4 u = make_float4(0.f, 0.f, 0.f, 0.f);
        int c2 = 0;
        if (t < 16) {
            int iu = __ldg(usu_1 + bg);
            u = ldh4(g_Es2 + iu * D + t * 4);
            int4 m0 = __ldg((const int4*)(usu_2 + bg * 8));
            int4 m1 = __ldg((const int4*)(usu_2 + bg * 8 + 4));
            c2 = (m0.x != 0) + (m0.y != 0) + (m0.z != 0) + (m0.w != 0)
               + (m1.x != 0) + (m1.y != 0) + (m1.z != 0) + (m1.w != 0);
        }

        const int4* ip = (const int4*)(usu_3 + (bg * 8 + g16) * 16);
        int4 i0 = __ldg(ip), i1 = __ldg(ip + 1), i2 = __ldg(ip + 2), i3 = __ldg(ip + 3);
        int cnt = (i0.x != 0) + (i0.y != 0) + (i0.z != 0) + (i0.w != 0)
                + (i1.x != 0) + (i1.y != 0) + (i1.z != 0) + (i1.w != 0)
                + (i2.x != 0) + (i2.y != 0) + (i2.z != 0) + (i2.w != 0)
                + (i3.x != 0) + (i3.y != 0) + (i3.z != 0) + (i3.w != 0);

        float sx = 0.f, sy = 0.f, sz = 0.f, sw = 0.f;
#define ACC(ix) { float4 v = ldh4(g_Es2 + (ix) * D + d4); \
                  sx += v.x; sy += v.y; sz += v.z; sw += v.w; }
        ACC(i0.x) ACC(i0.y) ACC(i0.z) ACC(i0.w)
        ACC(i1.x) ACC(i1.y) ACC(i1.z) ACC(i1.w)
        ACC(i2.x) ACC(i2.y) ACC(i2.z) ACC(i2.w)
        ACC(i3.x) ACC(i3.y) ACC(i3.z) ACC(i3.w)
#undef ACC
        float w = avgw(cnt);
        *(float4*)&shX[g16 * XS + d4] = make_float4(sx * w, sy * w, sz * w, sw * w);
        __syncthreads();

        // matvec W3: warp-chunk c4 (16 e = 4 quads), dims d2..d2+1, 8 rows
        {
            const __half* W3t = g_Wt2 + 4 * D * D;
            ull acc[8];
#pragma unroll
            for (int j = 0; j < 8; ++j) acc[j] = 0ull;
#pragma unroll
            for (int ep = 0; ep < 4; ++ep) {
                int e = c4 * 16 + ep * 4;
                ull w0 = ldw2(W3t + (e + 0) * D + d2);
                ull w1 = ldw2(W3t + (e + 1) * D + d2);
                ull w2 = ldw2(W3t + (e + 2) * D + d2);
                ull w3 = ldw2(W3t + (e + 3) * D + d2);
#pragma unroll
                for (int j = 0; j < 8; ++j) {
                    float4 xv = *(const float4*)&shX[j * XS + e];
                    fma2(acc[j], pack2(xv.x, xv.x), w0);
                    fma2(acc[j], pack2(xv.y, xv.y), w1);
                    fma2(acc[j], pack2(xv.z, xv.z), w2);
                    fma2(acc[j], pack2(xv.w, xv.w), w3);
                }
            }
#pragma unroll
            for (int j = 0; j < 8; ++j)
                *(float2*)&shP[c4][j][d2] = unpack2(acc[j]);
        }
        __syncthreads();

        // reduce 4 chunks + leaky + pairwise j via shfl
        {
            float rx = 0.f, ry = 0.f, rz = 0.f, rw = 0.f;
#pragma unroll
            for (int c = 0; c < 4; ++c) {
                float4 p = *(float4*)&shP[c][g16][d4];
                rx += p.x; ry += p.y; rz += p.z; rw += p.w;
            }
            rx = leaky(rx); ry = leaky(ry); rz = leaky(rz); rw = leaky(rw);
            rx += __shfl_down_sync(0xffffffffu, rx, 16);
            ry += __shfl_down_sync(0xffffffffu, ry, 16);
            rz += __shfl_down_sync(0xffffffffu, rz, 16);
            rw += __shfl_down_sync(0xffffffffu, rw, 16);
            if ((t & 16) == 0)
                *(float4*)&shL[t >> 5][d4] = make_float4(rx, ry, rz, rw);
        }
        __syncthreads();

        if (t < 16) {
            int dd = t * 4;
            float Sx = 0.f, Sy = 0.f, Sz = 0.f, Sw = 0.f;
#pragma unroll
            for (int wi = 0; wi < 4; ++wi) {
                float4 l = *(float4*)&shL[wi][dd];
                Sx += l.x; Sy += l.y; Sz += l.z; Sw += l.w;
            }
            float w2 = avgw(c2);
            Sx *= w2; Sy *= w2; Sz *= w2; Sw *= w2;
            *(float4*)&g_UA[bg * D + dd] = make_float4(u.x + Sx, u.y + Sy, u.z + Sz, u.w + Sw);
            *(float4*)&g_UB[bg * D + dd] = make_float4(Sx * u.x, Sy * u.y, Sz * u.z, Sw * u.w);
            __threadfence();
        }
        __syncthreads();
    } else {
        // ===================== dsd full path: one b per block ================
        b = blockIdx.x;

        float4 td4 = make_float4(0.f, 0.f, 0.f, 0.f);
        int c1 = 0;
        if (t < 16) {
            int lb = __ldg(label + b);
            td4 = ldh4(g_Ed2 + lb * D + t * 4);
            int4 m0 = __ldg((const int4*)(dsd_1 + b * 8));
            int4 m1 = __ldg((const int4*)(dsd_1 + b * 8 + 4));
            c1 = (m0.x != 0) + (m0.y != 0) + (m0.z != 0) + (m0.w != 0)
               + (m1.x != 0) + (m1.y != 0) + (m1.z != 0) + (m1.w != 0);
        }

        int ies = __ldg(dsd_1 + b * 8 + g16);
        const int4* ip = (const int4*)(dsd_2 + (b * 8 + g16) * 8);
        int4 i0 = __ldg(ip), i1 = __ldg(ip + 1);
        int cnt = (i0.x != 0) + (i0.y != 0) + (i0.z != 0) + (i0.w != 0)
                + (i1.x != 0) + (i1.y != 0) + (i1.z != 0) + (i1.w != 0);

        float4 es = ldh4(g_Es2 + ies * D + d4);
        float sx = 0.f, sy = 0.f, sz = 0.f, sw = 0.f;
#define ACC(ix) { float4 v = ldh4(g_Ed2 + (ix) * D + d4); \
                  sx += v.x; sy += v.y; sz += v.z; sw += v.w; }
        ACC(i0.x) ACC(i0.y) ACC(i0.z) ACC(i0.w)
        ACC(i1.x) ACC(i1.y) ACC(i1.z) ACC(i1.w)
#undef ACC
        float w = avgw(cnt);
        float ax = sx * w, ay = sy * w, az = sz * w, aw = sw * w;
        *(float4*)&shX[g16 * XS + d4] = make_float4(es.x + ax, es.y + ay, es.z + az, es.w + aw);
        *(float4*)&shY[g16 * XS + d4] = make_float4(ax * es.x, ay * es.y, az * es.z, aw * es.w);
        __syncthreads();

        // hop1 dual matvec W21/W22
        {
            const __half* W21t = g_Wt2 + 0 * D * D;
            const __half* W22t = g_Wt2 + 1 * D * D;
            ull acc[8];
#pragma unroll
            for (int j = 0; j < 8; ++j) acc[j] = 0ull;
#pragma unroll
            for (int ep = 0; ep < 4; ++ep) {
                int e = c4 * 16 + ep * 4;
                ull wa0 = ldw2(W21t + (e + 0) * D + d2);
                ull wa1 = ldw2(W21t + (e + 1) * D + d2);
                ull wa2 = ldw2(W21t + (e + 2) * D + d2);
                ull wa3 = ldw2(W21t + (e + 3) * D + d2);
                ull wb0 = ldw2(W22t + (e + 0) * D + d2);
                ull wb1 = ldw2(W22t + (e + 1) * D + d2);
                ull wb2 = ldw2(W22t + (e + 2) * D + d2);
                ull wb3 = ldw2(W22t + (e + 3) * D + d2);
#pragma unroll
                for (int j = 0; j < 8; ++j) {
                    float4 xv = *(const float4*)&shX[j * XS + e];
                    float4 yv = *(const float4*)&shY[j * XS + e];
                    fma2(acc[j], pack2(xv.x, xv.x), wa0);
                    fma2(acc[j], pack2(xv.y, xv.y), wa1);
                    fma2(acc[j], pack2(xv.z, xv.z), wa2);
                    fma2(acc[j], pack2(xv.w, xv.w), wa3);
                    fma2(acc[j], pack2(yv.x, yv.x), wb0);
                    fma2(acc[j], pack2(yv.y, yv.y), wb1);
                    fma2(acc[j], pack2(yv.z, yv.z), wb2);
                    fma2(acc[j], pack2(yv.w, yv.w), wb3);
                }
            }
#pragma unroll
            for (int j = 0; j < 8; ++j)
                *(float2*)&shP[c4][j][d2] = unpack2(acc[j]);
        }
        __syncthreads();

        // reduce + leaky + pairwise shfl
        {
            float rx = 0.f, ry = 0.f, rz = 0.f, rw = 0.f;
#pragma unroll
            for (int c = 0; c < 4; ++c) {
                float4 p = *(float4*)&shP[c][g16][d4];
                rx += p.x; ry += p.y; rz += p.z; rw += p.w;
            }
            rx = leaky(rx); ry = leaky(ry); rz = leaky(rz); rw = leaky(rw);
            rx += __shfl_down_sync(0xffffffffu, rx, 16);
            ry += __shfl_down_sync(0xffffffffu, ry, 16);
            rz += __shfl_down_sync(0xffffffffu, rz, 16);
            rw += __shfl_down_sync(0xffffffffu, rw, 16);
            if ((t & 16) == 0)
                *(float4*)&shL[t >> 5][d4] = make_float4(rx, ry, rz, rw);
        }
        __syncthreads();

        // hop2 inputs
        if (t < 16) {
            int dd = t * 4;
            float Ax = 0.f, Ay = 0.f, Az = 0.f, Aw = 0.f;
#pragma unroll
            for (int wi = 0; wi < 4; ++wi) {
                float4 l = *(float4*)&shL[wi][dd];
                Ax += l.x; Ay += l.y; Az += l.z; Aw += l.w;
            }
            float w1 = avgw(c1);
            Ax *= w1; Ay *= w1; Az *= w1; Aw *= w1;
            *(float4*)&shX[dd] = make_float4(Ax + td4.x, Ay + td4.y, Az + td4.z, Aw + td4.w);
            *(float4*)&shY[dd] = make_float4(Ax * td4.x, Ay * td4.y, Az * td4.z, Aw * td4.w);
        }
        __syncthreads();

        // hop2 dual matvec W11/W12 (1 row)
        {
            const __half* W11t = g_Wt2 + 2 * D * D;
            const __half* W12t = g_Wt2 + 3 * D * D;
            ull acc = 0ull;
#pragma unroll
            for (int ep = 0; ep < 4; ++ep) {
                int e = c4 * 16 + ep * 4;
                float4 xv = *(const float4*)&shX[e];
                float4 yv = *(const float4*)&shY[e];
                fma2(acc, pack2(xv.x, xv.x), ldw2(W11t + (e + 0) * D + d2));
                fma2(acc, pack2(xv.y, xv.y), ldw2(W11t + (e + 1) * D + d2));
                fma2(acc, pack2(xv.z, xv.z), ldw2(W11t + (e + 2) * D + d2));
                fma2(acc, pack2(xv.w, xv.w), ldw2(W11t + (e + 3) * D + d2));
                fma2(acc, pack2(yv.x, yv.x), ldw2(W12t + (e + 0) * D + d2));
                fma2(acc, pack2(yv.y, yv.y), ldw2(W12t + (e + 1) * D + d2));
                fma2(acc, pack2(yv.z, yv.z), ldw2(W12t + (e + 2) * D + d2));
                fma2(acc, pack2(yv.w, yv.w), ldw2(W12t + (e + 3) * D + d2));
            }
            *(float2*)&shP[c4][0][d2] = unpack2(acc);
        }
        __syncthreads();

        if (t < 16) {
            int dd = t * 4;
            float rx = 0.f, ry = 0.f, rz = 0.f, rw = 0.f;
#pragma unroll
            for (int c = 0; c < 4; ++c) {
                float4 p = *(float4*)&shP[c][0][dd];
                rx += p.x; ry += p.y; rz += p.z; rw += p.w;
            }
            *(float4*)&g_dise[b * D + dd] =
                make_float4(leaky(rx), leaky(ry), leaky(rz), leaky(rw));
            __threadfence();
        }
        __syncthreads();
    }

    // ======================= completion + finalization =======================
    if (t == 0) {
        int old = atomicAdd(&g_cnt[b], 1);
        if (old == 8) { __threadfence(); sFin = 1; } else sFin = 0;
    }
    __syncthreads();
    if (!sFin) return;

    // --- finalization: es1 matvec + i-avg + W1u matvec + dot with dise ---
    float4 dz = make_float4(0.f, 0.f, 0.f, 0.f);
    int c1u = 0;
    if (t < 16) {
        dz = *(const float4*)&g_dise[b * D + t * 4];
        int4 m0 = __ldg((const int4*)(usu_1 + b * 8));
        int4 m1 = __ldg((const int4*)(usu_1 + b * 8 + 4));
        c1u = (m0.x != 0) + (m0.y != 0) + (m0.z != 0) + (m0.w != 0)
            + (m1.x != 0) + (m1.y != 0) + (m1.z != 0) + (m1.w != 0);
    }
    *(float4*)&shX[g16 * XS + d4] = *(const float4*)&g_UA[(b * 8 + g16) * D + d4];
    *(float4*)&shY[g16 * XS + d4] = *(const float4*)&g_UB[(b * 8 + g16) * D + d4];
    __syncthreads();

    // es1 dual matvec W21u/W22u
    {
        const __half* W21t = g_Wt2 + 5 * D * D;
        const __half* W22t = g_Wt2 + 6 * D * D;
        ull acc[8];
#pragma unroll
        for (int j = 0; j < 8; ++j) acc[j] = 0ull;
#pragma unroll
        for (int ep = 0; ep < 4; ++ep) {
            int e = c4 * 16 + ep * 4;
            ull wa0 = ldw2(W21t + (e + 0) * D + d2);
            ull wa1 = ldw2(W21t + (e + 1) * D + d2);
            ull wa2 = ldw2(W21t + (e + 2) * D + d2);
            ull wa3 = ldw2(W21t + (e + 3) * D + d2);
            ull wb0 = ldw2(W22t + (e + 0) * D + d2);
            ull wb1 = ldw2(W22t + (e + 1) * D + d2);
            ull wb2 = ldw2(W22t + (e + 2) * D + d2);
            ull wb3 = ldw2(W22t + (e + 3) * D + d2);
#pragma unroll
            for (int j = 0; j < 8; ++j) {
                float4 xv = *(const float4*)&shX[j * XS + e];
                float4 yv = *(const float4*)&shY[j * XS + e];
                fma2(acc[j], pack2(xv.x, xv.x), wa0);
                fma2(acc[j], pack2(xv.y, xv.y), wa1);
                fma2(acc[j], pack2(xv.z, xv.z), wa2);
                fma2(acc[j], pack2(xv.w, xv.w), wa3);
                fma2(acc[j], pack2(yv.x, yv.x), wb0);
                fma2(acc[j], pack2(yv.y, yv.y), wb1);
                fma2(acc[j], pack2(yv.z, yv.z), wb2);
                fma2(acc[j], pack2(yv.w, yv.w), wb3);
            }
        }
#pragma unroll
        for (int j = 0; j < 8; ++j)
            *(float2*)&shP[c4][j][d2] = unpack2(acc[j]);
    }
    __syncthreads();

    // reduce + leaky + pairwise shfl
    {
        float rx = 0.f, ry = 0.f, rz = 0.f, rw = 0.f;
#pragma unroll
        for (int c = 0; c < 4; ++c) {
            float4 p = *(float4*)&shP[c][g16][d4];
            rx += p.x; ry += p.y; rz += p.z; rw += p.w;
        }
        rx = leaky(rx); ry = leaky(ry); rz = leaky(rz); rw = leaky(rw);
        rx += __shfl_down_sync(0xffffffffu, rx, 16);
        ry += __shfl_down_sync(0xffffffffu, ry, 16);
        rz += __shfl_down_sync(0xffffffffu, rz, 16);
        rw += __shfl_down_sync(0xffffffffu, rw, 16);
        if ((t & 16) == 0)
            *(float4*)&shL[t >> 5][d4] = make_float4(rx, ry, rz, rw);
    }
    __syncthreads();

    // i-avg
    if (t < 16) {
        int dd = t * 4;
        float Tx = 0.f, Ty = 0.f, Tz = 0.f, Tw = 0.f;
#pragma unroll
        for (int wi = 0; wi < 4; ++wi) {
            float4 l = *(float4*)&shL[wi][dd];
            Tx += l.x; Ty += l.y; Tz += l.z; Tw += l.w;
        }
        float w1 = avgw(c1u);
        *(float4*)&shX[dd] = make_float4(Tx * w1, Ty * w1, Tz * w1, Tw * w1);
    }
    __syncthreads();

    // emb_user matvec W1u (1 row)
    {
        const __half* W1t = g_Wt2 + 7 * D * D;
        ull acc = 0ull;
#pragma unroll
        for (int ep = 0; ep < 4; ++ep) {
            int e = c4 * 16 + ep * 4;
            float4 xv = *(const float4*)&shX[e];
            fma2(acc, pack2(xv.x, xv.x), ldw2(W1t + (e + 0) * D + d2));
            fma2(acc, pack2(xv.y, xv.y), ldw2(W1t + (e + 1) * D + d2));
            fma2(acc, pack2(xv.z, xv.z), ldw2(W1t + (e + 2) * D + d2));
            fma2(acc, pack2(xv.w, xv.w), ldw2(W1t + (e + 3) * D + d2));
        }
        *(float2*)&shP[c4][0][d2] = unpack2(acc);
    }
    __syncthreads();

    // final reduce + dot with emb_dise
    if (t < 16) {
        int dd = t * 4;
        float rx = 0.f, ry = 0.f, rz = 0.f, rw = 0.f;
#pragma unroll
        for (int c = 0; c < 4; ++c) {
            float4 p = *(float4*)&shP[c][0][dd];
            rx += p.x; ry += p.y; rz += p.z; rw += p.w;
        }
        float v = leaky(rx) * dz.x + leaky(ry) * dz.y +
                  leaky(rz) * dz.z + leaky(rw) * dz.w;
        v += __shfl_down_sync(0x0000ffffu, v, 8, 16);
        v += __shfl_down_sync(0x0000ffffu, v, 4, 16);
        v += __shfl_down_sync(0x0000ffffu, v, 2, 16);
        v += __shfl_down_sync(0x0000ffffu, v, 1, 16);
        if (t == 0) out[b] = v;
    }
}

// ---------------------------------------------------------------------------
extern "C" void kernel_launch(void* const* d_in, const int* in_sizes, int n_in,
                              void* d_out, int out_size) {
    const float* E_s = (const float*)d_in[0];
    const float* E_d = (const float*)d_in[1];
    // weights: W_dsd_21, W_dsd_22, W_dsd_11, W_dsd_12, W_usu_3, W_usu_21, W_usu_22, W_usu_1
    k_prep<<<PREP_GRID, 256>>>(E_s, E_d,
                               (const float*)d_in[2], (const float*)d_in[3],
                               (const float*)d_in[4], (const float*)d_in[5],
                               (const float*)d_in[6], (const float*)d_in[7],
                               (const float*)d_in[8], (const float*)d_in[9]);

    k_inner<<<NB * 9, 128>>>((const int*)d_in[10], (const int*)d_in[11],
                             (const int*)d_in[12], (const int*)d_in[13],
                             (const int*)d_in[14], (const int*)d_in[15],
                             (float*)d_out);
}